// round 6
// baseline (speedup 1.0000x reference)
#include <cuda_runtime.h>
#include <cuda_bf16.h>
#include <cstdint>

#define BB 8
#define SS 2048
#define DD 64
#define NSAMP 50

typedef unsigned long long u64;
typedef unsigned int u32;

__device__ float g_pe[BB * SS * DD];   // 4 MB scratch
__device__ float g_emb[BB * SS];       // 64 KB scratch

// ---- packed f32x2 helpers (Blackwell) -------------------------------------
__device__ __forceinline__ u64 pack2(float lo, float hi) {
    u64 r; asm("mov.b64 %0,{%1,%2};" : "=l"(r) : "f"(lo), "f"(hi)); return r;
}
__device__ __forceinline__ void fma2(u64& a, u64 x, u64 y) {
    asm("fma.rn.f32x2 %0,%1,%2,%0;" : "+l"(a) : "l"(x), "l"(y));
}
__device__ __forceinline__ float2 unpack2(u64 a) {
    float2 v; asm("mov.b64 {%0,%1},%2;" : "=f"(v.x), "=f"(v.y) : "l"(a)); return v;
}
__device__ __forceinline__ float softplusf(float x) {
    return fmaxf(x, 0.0f) + log1pf(expf(-fabsf(x)));
}
// ---- cp.async helpers -------------------------------------------------------
__device__ __forceinline__ void cp16(void* dst, const void* src) {
    unsigned sa = (unsigned)__cvta_generic_to_shared(dst);
    asm volatile("cp.async.ca.shared.global [%0],[%1],16;" :: "r"(sa), "l"(src));
}
__device__ __forceinline__ void cp4(void* dst, const void* src) {
    unsigned sa = (unsigned)__cvta_generic_to_shared(dst);
    asm volatile("cp.async.ca.shared.global [%0],[%1],4;" :: "r"(sa), "l"(src));
}
__device__ __forceinline__ void cp_commit() { asm volatile("cp.async.commit_group;"); }
__device__ __forceinline__ void cp_wait0()  { asm volatile("cp.async.wait_group 0;"); }

// ---- HMMA helpers (mma.sync, sm_80+ PTX: compiles under compute_103) -------
__device__ __forceinline__ u32 smem_u32(const void* p) {
    return (u32)__cvta_generic_to_shared(p);
}
#define LDSM_X4(r, a) \
    asm volatile("ldmatrix.sync.aligned.m8n8.x4.shared.b16 {%0,%1,%2,%3},[%4];" \
        : "=r"((r)[0]), "=r"((r)[1]), "=r"((r)[2]), "=r"((r)[3]) : "r"(a))
#define LDSM_X4T(r, a) \
    asm volatile("ldmatrix.sync.aligned.m8n8.x4.trans.shared.b16 {%0,%1,%2,%3},[%4];" \
        : "=r"((r)[0]), "=r"((r)[1]), "=r"((r)[2]), "=r"((r)[3]) : "r"(a))
#define MMA16816(c, a, b0, b1) \
    asm volatile("mma.sync.aligned.m16n8k16.row.col.f32.bf16.bf16.f32 " \
        "{%0,%1,%2,%3},{%4,%5,%6,%7},{%8,%9},{%0,%1,%2,%3};" \
        : "+f"((c)[0]), "+f"((c)[1]), "+f"((c)[2]), "+f"((c)[3]) \
        : "r"((a)[0]), "r"((a)[1]), "r"((a)[2]), "r"((a)[3]), "r"(b0), "r"(b1))

__device__ __forceinline__ uint2 bf16x4_hi(float4 v) {
    __nv_bfloat162 a = __floats2bfloat162_rn(v.x, v.y);
    __nv_bfloat162 b = __floats2bfloat162_rn(v.z, v.w);
    uint2 r; r.x = *(u32*)&a; r.y = *(u32*)&b; return r;
}
__device__ __forceinline__ uint2 bf16x4_lo(float4 v) {
    float hx = __bfloat162float(__float2bfloat16(v.x));
    float hy = __bfloat162float(__float2bfloat16(v.y));
    float hz = __bfloat162float(__float2bfloat16(v.z));
    float hw = __bfloat162float(__float2bfloat16(v.w));
    __nv_bfloat162 a = __floats2bfloat162_rn(v.x - hx, v.y - hy);
    __nv_bfloat162 b = __floats2bfloat162_rn(v.z - hz, v.w - hw);
    uint2 r; r.x = *(u32*)&a; r.y = *(u32*)&b; return r;
}

// ---------------------------------------------------------------------------
// Kernel 1: biased positional embedding + type embedding scalar
// ---------------------------------------------------------------------------
__global__ void pe_kernel(const int* __restrict__ etype,
                          const float* __restrict__ etime,
                          const float* __restrict__ Wt_pos,
                          const float* __restrict__ type_table) {
    int idx = blockIdx.x * blockDim.x + threadIdx.x;
    if (idx >= BB * SS * 32) return;
    int k = idx & 31;
    int s = (idx >> 5) & (SS - 1);
    int b = idx >> 16;
    int bs = b * SS + s;
    float t = etime[bs];
    float div = expf((float)(2 * k) * -0.14391156831212787f);
    float a = (float)s * div + t * Wt_pos[k];
    float sv, cv;
    __sincosf(a, &sv, &cv);
    g_pe[bs * DD + k]      = sv;
    g_pe[bs * DD + 32 + k] = cv;
    if (k == 0) {
        int ty = etype[bs];
        g_emb[bs] = (ty == 0) ? 0.0f : type_table[ty] * 8.0f;
    }
}

// ---------------------------------------------------------------------------
// Kernel 2: hidden = causal(scores) @ pe, fused LayerNorm (unchanged, passing)
// ---------------------------------------------------------------------------
__global__ __launch_bounds__(128) void hidden_kernel(
    const float* __restrict__ etime,
    const float* __restrict__ gamma,
    const float* __restrict__ beta,
    float* __restrict__ hidden_out) {
    __shared__ __align__(16) float pe_s[2][32][68];
    __shared__ float sc_s[32 * 33];
    __shared__ float ti_s[32], ei_s[32];
    __shared__ float tj_s[2][32], ej_s[2][32];

    const int b   = blockIdx.y;
    const int it  = 63 - blockIdx.x;
    const int tid = threadIdx.x;
    const int dg  = tid & 7;
    const int ig  = tid >> 3;
    const int si  = tid & 31;
    const int sjg = tid >> 5;

    const float4* gpe4 = (const float4*)g_pe;
    const float*  etb  = etime + b * SS;
    const float*  emb  = g_emb + b * SS;
    const int ntiles = it + 1;

    {
#pragma unroll
        for (int r = 0; r < 4; r++) {
            int idx = tid + 128 * r;
            int row = idx >> 4, c = idx & 15;
            cp16(&pe_s[0][row][c * 4], gpe4 + (b * SS + row) * 16 + c);
        }
        if (tid < 32) {
            cp4(&tj_s[0][tid], etb + tid);
            cp4(&ej_s[0][tid], emb + tid);
        }
        cp_commit();
    }
    if (tid < 32) {
        ti_s[tid] = etb[it * 32 + tid];
        ei_s[tid] = emb[it * 32 + tid];
    }
    const float4 gm0 = ((const float4*)gamma)[dg * 2];
    const float4 gm1 = ((const float4*)gamma)[dg * 2 + 1];
    const float4 bt0 = ((const float4*)beta)[dg * 2];
    const float4 bt1 = ((const float4*)beta)[dg * 2 + 1];

    u64 acc2[2][4];
#pragma unroll
    for (int k = 0; k < 2; k++)
#pragma unroll
        for (int m = 0; m < 4; m++) acc2[k][m] = 0ull;

    for (int jt = 0; jt < ntiles; jt++) {
        const int buf = jt & 1;
        cp_wait0();
        __syncthreads();

        if (jt + 1 < ntiles) {
            const int nb = buf ^ 1;
            const int j0 = (jt + 1) * 32;
#pragma unroll
            for (int r = 0; r < 4; r++) {
                int idx = tid + 128 * r;
                int row = idx >> 4, c = idx & 15;
                cp16(&pe_s[nb][row][c * 4], gpe4 + (b * SS + j0 + row) * 16 + c);
            }
            if (tid < 32) {
                cp4(&tj_s[nb][tid], etb + j0 + tid);
                cp4(&ej_s[nb][tid], emb + j0 + tid);
            }
            cp_commit();
        }

        {
            const float tii = ti_s[si];
            const float eii = ei_s[si];
            const int iglob = it * 32 + si;
#pragma unroll
            for (int m = 0; m < 8; m++) {
                const int jj = sjg * 8 + m;
                const int jglob = jt * 32 + jj;
                const float td = tii - tj_s[buf][jj];
                const float base = __fdividef(1.0f, 1.0f + 0.5f * td * td);
                const float gate =
                    __fdividef(1.0f, 1.0f + __expf(fabsf(eii - ej_s[buf][jj])));
                sc_s[si * 33 + jj] = (jglob <= iglob) ? base * gate : 0.0f;
            }
        }
        __syncthreads();

#pragma unroll 4
        for (int jj = 0; jj < 32; jj++) {
            const ulonglong2* pr = (const ulonglong2*)(&pe_s[buf][jj][dg * 8]);
            const ulonglong2 pa = pr[0];
            const ulonglong2 pb = pr[1];
            const float sv0 = sc_s[(2 * ig) * 33 + jj];
            const float sv1 = sc_s[(2 * ig + 1) * 33 + jj];
            const u64 s0 = pack2(sv0, sv0);
            const u64 s1 = pack2(sv1, sv1);
            fma2(acc2[0][0], s0, pa.x); fma2(acc2[0][1], s0, pa.y);
            fma2(acc2[0][2], s0, pb.x); fma2(acc2[0][3], s0, pb.y);
            fma2(acc2[1][0], s1, pa.x); fma2(acc2[1][1], s1, pa.y);
            fma2(acc2[1][2], s1, pb.x); fma2(acc2[1][3], s1, pb.y);
        }
    }

#pragma unroll
    for (int k = 0; k < 2; k++) {
        float f[8];
#pragma unroll
        for (int m = 0; m < 4; m++) {
            float2 v = unpack2(acc2[k][m]);
            f[2 * m] = v.x; f[2 * m + 1] = v.y;
        }
        float sum = 0.0f, sq = 0.0f;
#pragma unroll
        for (int m = 0; m < 8; m++) { sum += f[m]; sq += f[m] * f[m]; }
#pragma unroll
        for (int o = 1; o < 8; o <<= 1) {
            sum += __shfl_xor_sync(0xffffffffu, sum, o);
            sq  += __shfl_xor_sync(0xffffffffu, sq,  o);
        }
        const float mu  = sum * (1.0f / 64.0f);
        const float var = sq * (1.0f / 64.0f) - mu * mu;
        const float inv = rsqrtf(var + 1e-6f);
        const int row = it * 32 + 2 * ig + k;
        float* outp = hidden_out + ((size_t)(b * SS + row)) * 64 + dg * 8;
        float4 o0, o1;
        o0.x = (f[0] - mu) * inv * gm0.x + bt0.x;
        o0.y = (f[1] - mu) * inv * gm0.y + bt0.y;
        o0.z = (f[2] - mu) * inv * gm0.z + bt0.z;
        o0.w = (f[3] - mu) * inv * gm0.w + bt0.w;
        o1.x = (f[4] - mu) * inv * gm1.x + bt1.x;
        o1.y = (f[5] - mu) * inv * gm1.y + bt1.y;
        o1.z = (f[6] - mu) * inv * gm1.z + bt1.z;
        o1.w = (f[7] - mu) * inv * gm1.w + bt1.w;
        ((float4*)outp)[0] = o0;
        ((float4*)outp)[1] = o1;
    }
}

// ---------------------------------------------------------------------------
// Kernel 3: GAN decoder on HMMA (mma.sync m16n8k16 bf16, 3-term split).
// Block = one (b,s). A = noise [64(50+pad),136] bf16 (cols 0-63 hi, 64-127 lo,
// 272B row stride == 16 mod 128 -> conflict-free ldmatrix). B = W_noise^T
// [64,136] (cols 0-63 hi, 64-127 lo). D = Ah.Bh + Ah.Bl + Al.Bh (fp32 acc).
// Epilogue: z = D + proj[e]; mean_n softplus(sum_e relu(z)*wev[e]).
// ---------------------------------------------------------------------------
__global__ __launch_bounds__(128) void decoder_hmma_kernel(
    const float* __restrict__ noise,
    const float* __restrict__ W_in,
    const float* __restrict__ W_noise,
    const float* __restrict__ W_event,
    const float* __restrict__ hidden,
    float* __restrict__ mean_out) {
    __shared__ __align__(16) __nv_bfloat16 A_s[64][136];  // 17.4 KB
    __shared__ __align__(16) __nv_bfloat16 B_s[64][136];  // 17.4 KB
    __shared__ float h_s[64], pj_s[64], wev_s[64], srow[64];

    const int tid  = threadIdx.x;
    const int lane = tid & 31;
    const int wid  = tid >> 5;
    const int s = blockIdx.x, b = blockIdx.y;
    const int bs = b * SS + s;

    if (tid < 64) h_s[tid] = hidden[(size_t)bs * 64 + tid];
    else          wev_s[tid - 64] = W_event[tid - 64];

    // stage noise -> A planes (hi cols 0-63, lo cols 64-127)
    const float4* nsrc = (const float4*)(noise + (size_t)bs * NSAMP * 64);
    for (int idx = tid; idx < 800; idx += 128) {
        const float4 v = nsrc[idx];
        const int row = idx >> 4, c = (idx & 15) * 4;
        *(uint2*)&A_s[row][c]      = bf16x4_hi(v);
        *(uint2*)&A_s[row][64 + c] = bf16x4_lo(v);
    }
    // zero pad rows 50..63 (full 136 cols as u32)
    for (int i = tid; i < 14 * 68; i += 128) {
        const int row = 50 + i / 68, c = (i % 68) * 2;
        *(u32*)&A_s[row][c] = 0u;
    }
    // stage W_noise^T -> B planes: B[d][e]=hi, B[d][64+e]=lo
    {
        const float4* w4 = (const float4*)W_noise;
        for (int idx = tid; idx < 1024; idx += 128) {
            const float4 v = __ldg(w4 + idx);
            const int e = idx >> 4, d0 = (idx & 15) * 4;
            float vv[4] = {v.x, v.y, v.z, v.w};
#pragma unroll
            for (int j = 0; j < 4; j++) {
                const __nv_bfloat16 hi = __float2bfloat16(vv[j]);
                B_s[d0 + j][e]      = hi;
                B_s[d0 + j][64 + e] = __float2bfloat16(vv[j] - __bfloat162float(hi));
            }
        }
    }
    __syncthreads();

    // proj on warps 0-1 (overlaps MMA issue on warps 2-3)
    if (tid < 64) {
        const float4* wi = (const float4*)(W_in + tid * 64);
        float acc = 0.0f;
#pragma unroll
        for (int i = 0; i < 16; i++) {
            const float4 w = __ldg(wi + i);
            acc += w.x * h_s[4 * i]     + w.y * h_s[4 * i + 1]
                 + w.z * h_s[4 * i + 2] + w.w * h_s[4 * i + 3];
        }
        pj_s[tid] = acc;
    }

    // ---- HMMA mainloop ----
    const u32 Abase = smem_u32(A_s);
    const u32 Bbase = smem_u32(B_s);
    const int arow = 16 * wid + (lane & 15);
    const int acol = (lane >> 4) * 8;
    const int bk = (lane & 7) + 8 * ((lane >> 3) & 1);
    const int bn = 8 * (lane >> 4);

    float acc[8][4];
#pragma unroll
    for (int n = 0; n < 8; n++)
#pragma unroll
        for (int i = 0; i < 4; i++) acc[n][i] = 0.0f;

#pragma unroll
    for (int pass = 0; pass < 3; pass++) {
        const int pa = (pass == 2) ? 64 : 0;
        const int pb = (pass == 1) ? 64 : 0;
#pragma unroll
        for (int ks = 0; ks < 4; ks++) {
            u32 a[4];
            LDSM_X4(a, Abase + (u32)(arow * 272 + (pa + ks * 16 + acol) * 2));
#pragma unroll
            for (int ntp = 0; ntp < 4; ntp++) {
                u32 bb[4];
                LDSM_X4T(bb, Bbase + (u32)((ks * 16 + bk) * 272
                                           + (pb + ntp * 16 + bn) * 2));
                MMA16816(acc[2 * ntp],     a, bb[0], bb[1]);
                MMA16816(acc[2 * ntp + 1], a, bb[2], bb[3]);
            }
        }
    }
    __syncthreads();   // pj_s ready; srow below

    // ---- epilogue ----
#pragma unroll
    for (int h = 0; h < 2; h++) {
        const int row = 16 * wid + (lane >> 2) + 8 * h;
        float g = 0.0f;
#pragma unroll
        for (int nt = 0; nt < 8; nt++) {
#pragma unroll
            for (int j = 0; j < 2; j++) {
                const int e = nt * 8 + (lane & 3) * 2 + j;
                const float z = acc[nt][2 * h + j] + pj_s[e];
                g = fmaf(fmaxf(z, 0.0f), wev_s[e], g);
            }
        }
        g += __shfl_xor_sync(0xffffffffu, g, 1);
        g += __shfl_xor_sync(0xffffffffu, g, 2);
        if ((lane & 3) == 0 && row < NSAMP) srow[row] = softplusf(g);
    }
    __syncthreads();

    if (wid == 0) {
        float t = (lane < 25) ? srow[lane] + srow[lane + 25] : 0.0f;
#pragma unroll
        for (int o = 16; o > 0; o >>= 1)
            t += __shfl_xor_sync(0xffffffffu, t, o);
        if (lane == 0) mean_out[bs] = t * (1.0f / NSAMP);
    }
}

// ---------------------------------------------------------------------------
extern "C" void kernel_launch(void* const* d_in, const int* in_sizes, int n_in,
                              void* d_out, int out_size) {
    const int*   event_type = (const int*)d_in[0];
    const float* event_time = (const float*)d_in[1];
    const float* noise      = (const float*)d_in[3];
    const float* Wt_pos     = (const float*)d_in[4];
    const float* type_table = (const float*)d_in[5];
    const float* gamma      = (const float*)d_in[6];
    const float* beta       = (const float*)d_in[7];
    const float* W_in       = (const float*)d_in[8];
    const float* W_noise    = (const float*)d_in[9];
    const float* W_event    = (const float*)d_in[10];

    float* out        = (float*)d_out;
    float* mean_out   = out;               // [B,S]
    float* hidden_out = out + BB * SS;     // [B,S,D]

    pe_kernel<<<(BB * SS * 32 + 255) / 256, 256>>>(event_type, event_time,
                                                   Wt_pos, type_table);
    hidden_kernel<<<dim3(64, BB), 128>>>(event_time, gamma, beta, hidden_out);
    decoder_hmma_kernel<<<dim3(SS, BB), 128>>>(noise, W_in, W_noise, W_event,
                                               hidden_out, mean_out);
}

// round 8
// speedup vs baseline: 1.3599x; 1.3599x over previous
#include <cuda_runtime.h>
#include <cuda_bf16.h>
#include <cstdint>

#define BB 8
#define SS 2048
#define DD 64
#define NSAMP 50

typedef unsigned long long u64;
typedef unsigned int u32;

__device__ __nv_bfloat16 g_peh[BB * SS * DD];  // pe hi plane (2 MB)
__device__ __nv_bfloat16 g_pel[BB * SS * DD];  // pe lo plane (2 MB)
__device__ float g_emb[BB * SS];               // 64 KB

// ---- packed f32x2 helpers ---------------------------------------------------
__device__ __forceinline__ u64 pack2(float lo, float hi) {
    u64 r; asm("mov.b64 %0,{%1,%2};" : "=l"(r) : "f"(lo), "f"(hi)); return r;
}
__device__ __forceinline__ void fma2(u64& a, u64 x, u64 y) {
    asm("fma.rn.f32x2 %0,%1,%2,%0;" : "+l"(a) : "l"(x), "l"(y));
}
__device__ __forceinline__ u64 add2(u64 x, u64 y) {
    u64 r; asm("add.rn.f32x2 %0,%1,%2;" : "=l"(r) : "l"(x), "l"(y)); return r;
}
__device__ __forceinline__ float2 unpack2(u64 a) {
    float2 v; asm("mov.b64 {%0,%1},%2;" : "=f"(v.x), "=f"(v.y) : "l"(a)); return v;
}
__device__ __forceinline__ float softplusf(float x) {
    return fmaxf(x, 0.0f) + log1pf(expf(-fabsf(x)));
}
// ---- cp.async helpers ---------------------------------------------------------
__device__ __forceinline__ void cp16(void* dst, const void* src) {
    unsigned sa = (unsigned)__cvta_generic_to_shared(dst);
    asm volatile("cp.async.ca.shared.global [%0],[%1],16;" :: "r"(sa), "l"(src));
}
__device__ __forceinline__ void cp4(void* dst, const void* src) {
    unsigned sa = (unsigned)__cvta_generic_to_shared(dst);
    asm volatile("cp.async.ca.shared.global [%0],[%1],4;" :: "r"(sa), "l"(src));
}
__device__ __forceinline__ void cp_commit() { asm volatile("cp.async.commit_group;"); }
__device__ __forceinline__ void cp_wait0()  { asm volatile("cp.async.wait_group 0;"); }

// ---- HMMA helpers (sm_80+ PTX, compiles under compute_103) ------------------
__device__ __forceinline__ u32 smem_u32(const void* p) {
    return (u32)__cvta_generic_to_shared(p);
}
#define LDSM_X4(r, a) \
    asm volatile("ldmatrix.sync.aligned.m8n8.x4.shared.b16 {%0,%1,%2,%3},[%4];" \
        : "=r"((r)[0]), "=r"((r)[1]), "=r"((r)[2]), "=r"((r)[3]) : "r"(a))
#define LDSM_X4T(r, a) \
    asm volatile("ldmatrix.sync.aligned.m8n8.x4.trans.shared.b16 {%0,%1,%2,%3},[%4];" \
        : "=r"((r)[0]), "=r"((r)[1]), "=r"((r)[2]), "=r"((r)[3]) : "r"(a))
#define MMA16816(c, a, b0, b1) \
    asm volatile("mma.sync.aligned.m16n8k16.row.col.f32.bf16.bf16.f32 " \
        "{%0,%1,%2,%3},{%4,%5,%6,%7},{%8,%9},{%0,%1,%2,%3};" \
        : "+f"((c)[0]), "+f"((c)[1]), "+f"((c)[2]), "+f"((c)[3]) \
        : "r"((a)[0]), "r"((a)[1]), "r"((a)[2]), "r"((a)[3]), "r"(b0), "r"(b1))

// ---------------------------------------------------------------------------
// Kernel 1: pe (bf16 hi/lo planes) + type embedding scalar
// ---------------------------------------------------------------------------
__global__ void pe_kernel(const int* __restrict__ etype,
                          const float* __restrict__ etime,
                          const float* __restrict__ Wt_pos,
                          const float* __restrict__ type_table) {
    int idx = blockIdx.x * blockDim.x + threadIdx.x;
    if (idx >= BB * SS * 32) return;
    int k = idx & 31;
    int s = (idx >> 5) & (SS - 1);
    int b = idx >> 16;
    int bs = b * SS + s;
    float t = etime[bs];
    float div = expf((float)(2 * k) * -0.14391156831212787f);
    float a = (float)s * div + t * Wt_pos[k];
    float sv, cv;
    __sincosf(a, &sv, &cv);
    __nv_bfloat16 sh = __float2bfloat16(sv);
    __nv_bfloat16 ch = __float2bfloat16(cv);
    g_peh[bs * DD + k]      = sh;
    g_pel[bs * DD + k]      = __float2bfloat16(sv - __bfloat162float(sh));
    g_peh[bs * DD + 32 + k] = ch;
    g_pel[bs * DD + 32 + k] = __float2bfloat16(cv - __bfloat162float(ch));
    if (k == 0) {
        int ty = etype[bs];
        g_emb[bs] = (ty == 0) ? 0.0f : type_table[ty] * 8.0f;
    }
}

// ---------------------------------------------------------------------------
// Kernel 2: hidden = causal(scores) @ pe on HMMA, fused LayerNorm.
// Block = (b, 64-row i-tile). A = scores [64][64+64 hi|lo] bf16 (built per
// j-tile from the RQ-kernel formula), B = pe tile [64 j][64+64 hi|lo] bf16
// (cp.async from precomputed planes, load hidden behind score computation).
// D accumulates in fp32 across all j-tiles; 3-term split per tile.
// ---------------------------------------------------------------------------
__global__ __launch_bounds__(128) void hidden_hmma_kernel(
    const float* __restrict__ etime,
    const float* __restrict__ gamma,
    const float* __restrict__ beta,
    float* __restrict__ hidden_out) {
    __shared__ __align__(16) __nv_bfloat16 A_s[64][136];  // 17.4 KB
    __shared__ __align__(16) __nv_bfloat16 B_s[64][136];  // 17.4 KB
    __shared__ float ti_s[64], ei_s[64];
    __shared__ float tj_s[2][64], ej_s[2][64];
    __shared__ float gm_s[64], bt_s[64];

    const int b   = blockIdx.y;
    const int T   = 31 - blockIdx.x;    // heavy i-tiles first
    const int tid = threadIdx.x;
    const int lane = tid & 31;
    const int wid  = tid >> 5;

    const float* etb = etime + b * SS;
    const float* emb = g_emb + b * SS;
    const __nv_bfloat16* peh = g_peh + (size_t)b * SS * DD;
    const __nv_bfloat16* pel = g_pel + (size_t)b * SS * DD;

    if (tid < 64) {
        ti_s[tid] = etb[T * 64 + tid];
        gm_s[tid] = gamma[tid];
        tj_s[0][tid] = etb[tid];
        ej_s[0][tid] = emb[tid];
    } else {
        ei_s[tid - 64] = emb[T * 64 + tid - 64];
        bt_s[tid - 64] = beta[tid - 64];
    }

    float acc[8][4];
#pragma unroll
    for (int n = 0; n < 8; n++)
#pragma unroll
        for (int i = 0; i < 4; i++) acc[n][i] = 0.0f;

    const u32 Abase = smem_u32(A_s);
    const u32 Bbase = smem_u32(B_s);
    const int arow = 16 * wid + (lane & 15);
    const int acol = (lane >> 4) * 8;
    const int bk = (lane & 7) + 8 * ((lane >> 3) & 1);
    const int bn = 8 * (lane >> 4);
    const int srow = tid >> 1;           // score row 0..63
    const int sjh  = (tid & 1) * 32;     // j-half
    const int iglob = T * 64 + srow;

    __syncthreads();

    for (int jt = 0; jt <= T; jt++) {
        const int buf = jt & 1;
        const int j0 = jt * 64;

        // issue cp.async: B tile (pe hi/lo) for jt + tj/ej for jt+1
        {
#pragma unroll
            for (int r = 0; r < 8; r++) {
                const int idx = tid + 128 * r;        // 0..1023
                const int row = idx >> 4;
                const int pl  = (idx >> 3) & 1;
                const int c   = idx & 7;
                const __nv_bfloat16* src = pl ? pel : peh;
                cp16(&B_s[row][pl * 64 + c * 8],
                     src + (j0 + row) * DD + c * 8);
            }
            if (jt < T) {
                const int nb = buf ^ 1;
                if (tid < 64) cp4(&tj_s[nb][tid], etb + j0 + 64 + tid);
                else          cp4(&ej_s[nb][tid - 64], emb + j0 + 64 + tid - 64);
            }
            cp_commit();
        }

        // scores for jt (overlaps B load): 32 evals/thread -> A_s hi|lo
        {
            const float tii = ti_s[srow];
            const float eii = ei_s[srow];
#pragma unroll 4
            for (int q = 0; q < 16; q++) {
                float sc[2];
#pragma unroll
                for (int j = 0; j < 2; j++) {
                    const int jj = sjh + 2 * q + j;
                    const float td = tii - tj_s[buf][jj];
                    const float ae = fabsf(eii - ej_s[buf][jj]);
                    const float prod = (1.0f + 0.5f * td * td) * (1.0f + __expf(ae));
                    sc[j] = (j0 + jj <= iglob) ? __fdividef(1.0f, prod) : 0.0f;
                }
                const __nv_bfloat162 hi2 = __floats2bfloat162_rn(sc[0], sc[1]);
                const float r0 = sc[0] - __bfloat162float(__low2bfloat16(hi2));
                const float r1 = sc[1] - __bfloat162float(__high2bfloat16(hi2));
                const __nv_bfloat162 lo2 = __floats2bfloat162_rn(r0, r1);
                *(u32*)&A_s[srow][sjh + 2 * q]      = *(const u32*)&hi2;
                *(u32*)&A_s[srow][64 + sjh + 2 * q] = *(const u32*)&lo2;
            }
        }
        cp_wait0();
        __syncthreads();                  // A scores + B pe ready

        // MMA: 3 passes (Ah.Bh, Ah.Bl, Al.Bh)
#pragma unroll
        for (int pass = 0; pass < 3; pass++) {
            const int pa = (pass == 2) ? 64 : 0;
            const int pb = (pass == 1) ? 64 : 0;
#pragma unroll
            for (int ks = 0; ks < 4; ks++) {
                u32 a[4];
                LDSM_X4(a, Abase + (u32)(arow * 272 + (pa + ks * 16 + acol) * 2));
#pragma unroll
                for (int ntp = 0; ntp < 4; ntp++) {
                    u32 bb[4];
                    LDSM_X4T(bb, Bbase + (u32)((ks * 16 + bk) * 272
                                               + (pb + ntp * 16 + bn) * 2));
                    MMA16816(acc[2 * ntp],     a, bb[0], bb[1]);
                    MMA16816(acc[2 * ntp + 1], a, bb[2], bb[3]);
                }
            }
        }
        __syncthreads();                  // A/B free for next tile
    }

    // ---- fused LayerNorm epilogue ----
#pragma unroll
    for (int h = 0; h < 2; h++) {
        const int row = 16 * wid + (lane >> 2) + 8 * h;
        float sum = 0.0f, sq = 0.0f;
#pragma unroll
        for (int nt = 0; nt < 8; nt++) {
#pragma unroll
            for (int j = 0; j < 2; j++) {
                const float v = acc[nt][2 * h + j];
                sum += v; sq += v * v;
            }
        }
        sum += __shfl_xor_sync(0xffffffffu, sum, 1);
        sq  += __shfl_xor_sync(0xffffffffu, sq,  1);
        sum += __shfl_xor_sync(0xffffffffu, sum, 2);
        sq  += __shfl_xor_sync(0xffffffffu, sq,  2);
        const float mu  = sum * (1.0f / 64.0f);
        const float var = sq * (1.0f / 64.0f) - mu * mu;
        const float inv = rsqrtf(var + 1e-6f);
        float* outp = hidden_out + ((size_t)(b * SS + T * 64 + row)) * 64;
#pragma unroll
        for (int nt = 0; nt < 8; nt++) {
            const int d0 = nt * 8 + (lane & 3) * 2;
            float2 o;
            o.x = (acc[nt][2 * h]     - mu) * inv * gm_s[d0]     + bt_s[d0];
            o.y = (acc[nt][2 * h + 1] - mu) * inv * gm_s[d0 + 1] + bt_s[d0 + 1];
            *(float2*)(outp + d0) = o;
        }
    }
}

// ---------------------------------------------------------------------------
// Kernel 3: GAN decoder (measured-best f32x2 version, unchanged).
// ---------------------------------------------------------------------------
__global__ __launch_bounds__(128, 4) void decoder_kernel(
    const float* __restrict__ noise,
    const float* __restrict__ W_in,
    const float* __restrict__ W_noise,
    const float* __restrict__ W_event,
    const float* __restrict__ hidden,
    float* __restrict__ mean_out) {
    __shared__ __align__(16) float win_s[64][68];
    __shared__ __align__(16) float4 nbuf[2][800];
    __shared__ float h_s[2][64];
    __shared__ float gpart[NSAMP][2];
    __shared__ float pred[2];

    const int s0 = blockIdx.x * 4, b = blockIdx.y;
    const int bs0 = b * SS + s0;
    const int tid   = threadIdx.x;
    const int lane  = tid & 31;
    const int e     = tid & 63;
    const int ngrp  = tid >> 6;
    const int whalf = (tid >> 5) & 1;
    const int warp  = tid >> 5;

    {
        const float4* wn4 = (const float4*)W_noise;
        const float4* wi4 = (const float4*)W_in;
#pragma unroll
        for (int r = 0; r < 8; r++) {
            int idx = tid + 128 * r;
            cp16(&nbuf[0][idx], wn4 + idx);
            int row = idx >> 4, c = idx & 15;
            cp16(&win_s[row][c * 4], wi4 + idx);
        }
        cp_commit();
        cp_wait0();
    }
    __syncthreads();

    u64 wr[32];
    {
        const ulonglong2* q = (const ulonglong2*)&nbuf[0][e * 16];
#pragma unroll
        for (int i = 0; i < 16; i++) {
            const ulonglong2 v = q[i];
            wr[2 * i] = v.x; wr[2 * i + 1] = v.y;
        }
    }
    const float wev = W_event[e];
    __syncthreads();

    {
        const float4* src = (const float4*)(noise + (size_t)bs0 * NSAMP * 64);
#pragma unroll
        for (int r = 0; r < 7; r++) {
            int idx = tid + 128 * r;
            if (idx < 800) cp16(&nbuf[0][idx], src + idx);
        }
        if (tid < 64) cp4(&h_s[0][tid], hidden + (size_t)bs0 * 64 + tid);
        cp_commit();
    }

    for (int v = 0; v < 4; v++) {
        const int buf = v & 1;
        const int bs = bs0 + v;
        cp_wait0();
        __syncthreads();

        if (v < 3) {
            const float4* src =
                (const float4*)(noise + (size_t)(bs + 1) * NSAMP * 64);
            const int nb = buf ^ 1;
#pragma unroll
            for (int r = 0; r < 7; r++) {
                int idx = tid + 128 * r;
                if (idx < 800) cp16(&nbuf[nb][idx], src + idx);
            }
            if (tid < 64) cp4(&h_s[nb][tid], hidden + (size_t)(bs + 1) * 64 + tid);
            cp_commit();
        }

        float pj = 0.0f;
#pragma unroll
        for (int i = 0; i < 16; i++) {
            const float4 w = *(const float4*)&win_s[e][i * 4];
            pj += w.x * h_s[buf][4 * i]     + w.y * h_s[buf][4 * i + 1]
                + w.z * h_s[buf][4 * i + 2] + w.w * h_s[buf][4 * i + 3];
        }

        for (int k = 0; k < 25; k++) {
            const int n = ngrp + 2 * k;
            const ulonglong2* row = (const ulonglong2*)&nbuf[buf][n * 16];
            u64 acc[8];
#pragma unroll
            for (int m = 0; m < 8; m++) acc[m] = 0ull;
#pragma unroll
            for (int i = 0; i < 16; i++) {
                const ulonglong2 nv = row[i];
                fma2(acc[(2 * i) & 7],     nv.x, wr[2 * i]);
                fma2(acc[(2 * i + 1) & 7], nv.y, wr[2 * i + 1]);
            }
            u64 a0 = add2(add2(acc[0], acc[4]), add2(acc[2], acc[6]));
            u64 a1 = add2(add2(acc[1], acc[5]), add2(acc[3], acc[7]));
            float2 vv = unpack2(add2(a0, a1));
            float g = fmaxf(pj + vv.x + vv.y, 0.0f) * wev;
#pragma unroll
            for (int o = 16; o > 0; o >>= 1)
                g += __shfl_xor_sync(0xffffffffu, g, o);
            if (lane == 0) gpart[n][whalf] = g;
        }
        __syncthreads();

        if (tid < 64) {
            float t = 0.0f;
            if (tid < NSAMP) t = softplusf(gpart[tid][0] + gpart[tid][1]);
#pragma unroll
            for (int o = 16; o > 0; o >>= 1)
                t += __shfl_xor_sync(0xffffffffu, t, o);
            if (lane == 0) pred[warp] = t;
        }
        __syncthreads();
        if (tid == 0) mean_out[bs] = (pred[0] + pred[1]) * (1.0f / NSAMP);
    }
}

// ---------------------------------------------------------------------------
extern "C" void kernel_launch(void* const* d_in, const int* in_sizes, int n_in,
                              void* d_out, int out_size) {
    const int*   event_type = (const int*)d_in[0];
    const float* event_time = (const float*)d_in[1];
    const float* noise      = (const float*)d_in[3];
    const float* Wt_pos     = (const float*)d_in[4];
    const float* type_table = (const float*)d_in[5];
    const float* gamma      = (const float*)d_in[6];
    const float* beta       = (const float*)d_in[7];
    const float* W_in       = (const float*)d_in[8];
    const float* W_noise    = (const float*)d_in[9];
    const float* W_event    = (const float*)d_in[10];

    float* out        = (float*)d_out;
    float* mean_out   = out;               // [B,S]
    float* hidden_out = out + BB * SS;     // [B,S,D]

    pe_kernel<<<(BB * SS * 32 + 255) / 256, 256>>>(event_type, event_time,
                                                   Wt_pos, type_table);
    hidden_hmma_kernel<<<dim3(32, BB), 128>>>(event_time, gamma, beta, hidden_out);
    decoder_kernel<<<dim3(SS / 4, BB), 128>>>(noise, W_in, W_noise, W_event,
                                              hidden_out, mean_out);
}

// round 9
// speedup vs baseline: 2.4092x; 1.7716x over previous
#include <cuda_runtime.h>
#include <cuda_bf16.h>
#include <cstdint>

#define BB 8
#define SS 2048
#define DD 64
#define NSAMP 50

typedef unsigned long long u64;
typedef unsigned int u32;

__device__ __nv_bfloat16 g_peh[BB * SS * DD];   // pe hi plane (2 MB)
__device__ __nv_bfloat16 g_pel[BB * SS * DD];   // pe lo plane (2 MB)
__device__ float g_emb[BB * SS];                // 64 KB
__device__ __nv_bfloat16 g_wplanes[64 * 136];   // W_noise^T bf16 hi|lo, B_s layout
__device__ float g_proj[BB * SS * DD];          // proj = hidden @ W_in^T (4 MB)

// ---- misc helpers -----------------------------------------------------------
__device__ __forceinline__ float softplusf(float x) {
    return fmaxf(x, 0.0f) + log1pf(expf(-fabsf(x)));
}
__device__ __forceinline__ void cp16(void* dst, const void* src) {
    unsigned sa = (unsigned)__cvta_generic_to_shared(dst);
    asm volatile("cp.async.ca.shared.global [%0],[%1],16;" :: "r"(sa), "l"(src));
}
__device__ __forceinline__ void cp4(void* dst, const void* src) {
    unsigned sa = (unsigned)__cvta_generic_to_shared(dst);
    asm volatile("cp.async.ca.shared.global [%0],[%1],4;" :: "r"(sa), "l"(src));
}
__device__ __forceinline__ void cp_commit() { asm volatile("cp.async.commit_group;"); }
__device__ __forceinline__ void cp_wait0()  { asm volatile("cp.async.wait_group 0;"); }

// ---- HMMA helpers (sm_80+ PTX) -----------------------------------------------
__device__ __forceinline__ u32 smem_u32(const void* p) {
    return (u32)__cvta_generic_to_shared(p);
}
#define LDSM_X4(r, a) \
    asm volatile("ldmatrix.sync.aligned.m8n8.x4.shared.b16 {%0,%1,%2,%3},[%4];" \
        : "=r"((r)[0]), "=r"((r)[1]), "=r"((r)[2]), "=r"((r)[3]) : "r"(a))
#define LDSM_X4T(r, a) \
    asm volatile("ldmatrix.sync.aligned.m8n8.x4.trans.shared.b16 {%0,%1,%2,%3},[%4];" \
        : "=r"((r)[0]), "=r"((r)[1]), "=r"((r)[2]), "=r"((r)[3]) : "r"(a))
#define MMA16816(c, a, b0, b1) \
    asm volatile("mma.sync.aligned.m16n8k16.row.col.f32.bf16.bf16.f32 " \
        "{%0,%1,%2,%3},{%4,%5,%6,%7},{%8,%9},{%0,%1,%2,%3};" \
        : "+f"((c)[0]), "+f"((c)[1]), "+f"((c)[2]), "+f"((c)[3]) \
        : "r"((a)[0]), "r"((a)[1]), "r"((a)[2]), "r"((a)[3]), "r"(b0), "r"(b1))

__device__ __forceinline__ uint2 bf16x4_hi(float4 v) {
    __nv_bfloat162 a = __floats2bfloat162_rn(v.x, v.y);
    __nv_bfloat162 b = __floats2bfloat162_rn(v.z, v.w);
    uint2 r; r.x = *(u32*)&a; r.y = *(u32*)&b; return r;
}
__device__ __forceinline__ uint2 bf16x4_lo(float4 v) {
    float hx = __bfloat162float(__float2bfloat16(v.x));
    float hy = __bfloat162float(__float2bfloat16(v.y));
    float hz = __bfloat162float(__float2bfloat16(v.z));
    float hw = __bfloat162float(__float2bfloat16(v.w));
    __nv_bfloat162 a = __floats2bfloat162_rn(v.x - hx, v.y - hy);
    __nv_bfloat162 b = __floats2bfloat162_rn(v.z - hz, v.w - hw);
    uint2 r; r.x = *(u32*)&a; r.y = *(u32*)&b; return r;
}

// ---------------------------------------------------------------------------
// Kernel 1: pe (bf16 hi/lo planes) + type embedding scalar
// ---------------------------------------------------------------------------
__global__ void pe_kernel(const int* __restrict__ etype,
                          const float* __restrict__ etime,
                          const float* __restrict__ Wt_pos,
                          const float* __restrict__ type_table) {
    int idx = blockIdx.x * blockDim.x + threadIdx.x;
    if (idx >= BB * SS * 32) return;
    int k = idx & 31;
    int s = (idx >> 5) & (SS - 1);
    int b = idx >> 16;
    int bs = b * SS + s;
    float t = etime[bs];
    float div = expf((float)(2 * k) * -0.14391156831212787f);
    float a = (float)s * div + t * Wt_pos[k];
    float sv, cv;
    __sincosf(a, &sv, &cv);
    __nv_bfloat16 sh = __float2bfloat16(sv);
    __nv_bfloat16 ch = __float2bfloat16(cv);
    g_peh[bs * DD + k]      = sh;
    g_pel[bs * DD + k]      = __float2bfloat16(sv - __bfloat162float(sh));
    g_peh[bs * DD + 32 + k] = ch;
    g_pel[bs * DD + 32 + k] = __float2bfloat16(cv - __bfloat162float(ch));
    if (k == 0) {
        int ty = etype[bs];
        g_emb[bs] = (ty == 0) ? 0.0f : type_table[ty] * 8.0f;
    }
}

// ---------------------------------------------------------------------------
// Kernel 1b: W_noise -> bf16 hi|lo planes, pre-laid-out as B_s[64][136].
// B_s[d][e] = hi(W_noise[e][d]); B_s[d][64+e] = lo.
// ---------------------------------------------------------------------------
__global__ void prep_w_kernel(const float* __restrict__ W_noise) {
    int idx = blockIdx.x * blockDim.x + threadIdx.x;
    if (idx >= 4096) return;
    int e = idx >> 6, d = idx & 63;
    float v = W_noise[idx];
    __nv_bfloat16 hi = __float2bfloat16(v);
    g_wplanes[d * 136 + e]      = hi;
    g_wplanes[d * 136 + 64 + e] = __float2bfloat16(v - __bfloat162float(hi));
}

// ---------------------------------------------------------------------------
// Kernel 2: hidden = causal(scores) @ pe on HMMA, fused LayerNorm (R7, passing)
// ---------------------------------------------------------------------------
__global__ __launch_bounds__(128) void hidden_hmma_kernel(
    const float* __restrict__ etime,
    const float* __restrict__ gamma,
    const float* __restrict__ beta,
    float* __restrict__ hidden_out) {
    __shared__ __align__(16) __nv_bfloat16 A_s[64][136];
    __shared__ __align__(16) __nv_bfloat16 B_s[64][136];
    __shared__ float ti_s[64], ei_s[64];
    __shared__ float tj_s[2][64], ej_s[2][64];
    __shared__ float gm_s[64], bt_s[64];

    const int b   = blockIdx.y;
    const int T   = 31 - blockIdx.x;
    const int tid = threadIdx.x;
    const int lane = tid & 31;
    const int wid  = tid >> 5;

    const float* etb = etime + b * SS;
    const float* emb = g_emb + b * SS;
    const __nv_bfloat16* peh = g_peh + (size_t)b * SS * DD;
    const __nv_bfloat16* pel = g_pel + (size_t)b * SS * DD;

    if (tid < 64) {
        ti_s[tid] = etb[T * 64 + tid];
        gm_s[tid] = gamma[tid];
        tj_s[0][tid] = etb[tid];
        ej_s[0][tid] = emb[tid];
    } else {
        ei_s[tid - 64] = emb[T * 64 + tid - 64];
        bt_s[tid - 64] = beta[tid - 64];
    }

    float acc[8][4];
#pragma unroll
    for (int n = 0; n < 8; n++)
#pragma unroll
        for (int i = 0; i < 4; i++) acc[n][i] = 0.0f;

    const u32 Abase = smem_u32(A_s);
    const u32 Bbase = smem_u32(B_s);
    const int arow = 16 * wid + (lane & 15);
    const int acol = (lane >> 4) * 8;
    const int bk = (lane & 7) + 8 * ((lane >> 3) & 1);
    const int bn = 8 * (lane >> 4);
    const int srow = tid >> 1;
    const int sjh  = (tid & 1) * 32;
    const int iglob = T * 64 + srow;

    __syncthreads();

    for (int jt = 0; jt <= T; jt++) {
        const int buf = jt & 1;
        const int j0 = jt * 64;
        {
#pragma unroll
            for (int r = 0; r < 8; r++) {
                const int idx = tid + 128 * r;
                const int row = idx >> 4;
                const int pl  = (idx >> 3) & 1;
                const int c   = idx & 7;
                const __nv_bfloat16* src = pl ? pel : peh;
                cp16(&B_s[row][pl * 64 + c * 8], src + (j0 + row) * DD + c * 8);
            }
            if (jt < T) {
                const int nb = buf ^ 1;
                if (tid < 64) cp4(&tj_s[nb][tid], etb + j0 + 64 + tid);
                else          cp4(&ej_s[nb][tid - 64], emb + j0 + 64 + tid - 64);
            }
            cp_commit();
        }
        {
            const float tii = ti_s[srow];
            const float eii = ei_s[srow];
#pragma unroll 4
            for (int q = 0; q < 16; q++) {
                float sc[2];
#pragma unroll
                for (int j = 0; j < 2; j++) {
                    const int jj = sjh + 2 * q + j;
                    const float td = tii - tj_s[buf][jj];
                    const float ae = fabsf(eii - ej_s[buf][jj]);
                    const float prod = (1.0f + 0.5f * td * td) * (1.0f + __expf(ae));
                    sc[j] = (j0 + jj <= iglob) ? __fdividef(1.0f, prod) : 0.0f;
                }
                const __nv_bfloat162 hi2 = __floats2bfloat162_rn(sc[0], sc[1]);
                const float r0 = sc[0] - __bfloat162float(__low2bfloat16(hi2));
                const float r1 = sc[1] - __bfloat162float(__high2bfloat16(hi2));
                const __nv_bfloat162 lo2 = __floats2bfloat162_rn(r0, r1);
                *(u32*)&A_s[srow][sjh + 2 * q]      = *(const u32*)&hi2;
                *(u32*)&A_s[srow][64 + sjh + 2 * q] = *(const u32*)&lo2;
            }
        }
        cp_wait0();
        __syncthreads();

#pragma unroll
        for (int pass = 0; pass < 3; pass++) {
            const int pa = (pass == 2) ? 64 : 0;
            const int pb = (pass == 1) ? 64 : 0;
#pragma unroll
            for (int ks = 0; ks < 4; ks++) {
                u32 a[4];
                LDSM_X4(a, Abase + (u32)(arow * 272 + (pa + ks * 16 + acol) * 2));
#pragma unroll
                for (int ntp = 0; ntp < 4; ntp++) {
                    u32 bb[4];
                    LDSM_X4T(bb, Bbase + (u32)((ks * 16 + bk) * 272
                                               + (pb + ntp * 16 + bn) * 2));
                    MMA16816(acc[2 * ntp],     a, bb[0], bb[1]);
                    MMA16816(acc[2 * ntp + 1], a, bb[2], bb[3]);
                }
            }
        }
        __syncthreads();
    }

#pragma unroll
    for (int h = 0; h < 2; h++) {
        const int row = 16 * wid + (lane >> 2) + 8 * h;
        float sum = 0.0f, sq = 0.0f;
#pragma unroll
        for (int nt = 0; nt < 8; nt++) {
#pragma unroll
            for (int j = 0; j < 2; j++) {
                const float v = acc[nt][2 * h + j];
                sum += v; sq += v * v;
            }
        }
        sum += __shfl_xor_sync(0xffffffffu, sum, 1);
        sq  += __shfl_xor_sync(0xffffffffu, sq,  1);
        sum += __shfl_xor_sync(0xffffffffu, sum, 2);
        sq  += __shfl_xor_sync(0xffffffffu, sq,  2);
        const float mu  = sum * (1.0f / 64.0f);
        const float var = sq * (1.0f / 64.0f) - mu * mu;
        const float inv = rsqrtf(var + 1e-6f);
        float* outp = hidden_out + ((size_t)(b * SS + T * 64 + row)) * 64;
#pragma unroll
        for (int nt = 0; nt < 8; nt++) {
            const int d0 = nt * 8 + (lane & 3) * 2;
            float2 o;
            o.x = (acc[nt][2 * h]     - mu) * inv * gm_s[d0]     + bt_s[d0];
            o.y = (acc[nt][2 * h + 1] - mu) * inv * gm_s[d0 + 1] + bt_s[d0 + 1];
            *(float2*)(outp + d0) = o;
        }
    }
}

// ---------------------------------------------------------------------------
// Kernel 2b: proj[bs][e] = W_in[e,:] . hidden[bs,:]  (exact fp32)
// Block = 8 steps, 128 threads; W_in staged in smem.
// ---------------------------------------------------------------------------
__global__ __launch_bounds__(128) void proj_kernel(
    const float* __restrict__ W_in,
    const float* __restrict__ hidden) {
    __shared__ float win[64][65];
    __shared__ float h8[8][64];

    const int tid = threadIdx.x;
    const int bs0 = blockIdx.x * 8;

    {
        const float4* wi4 = (const float4*)W_in;
#pragma unroll
        for (int r = 0; r < 8; r++) {
            const int idx = tid + 128 * r;
            const float4 w = __ldg(wi4 + idx);
            const int row = idx >> 4, c = (idx & 15) * 4;
            win[row][c] = w.x; win[row][c + 1] = w.y;
            win[row][c + 2] = w.z; win[row][c + 3] = w.w;
        }
        const float4* h4 = (const float4*)(hidden + (size_t)bs0 * 64);
#pragma unroll
        for (int r = 0; r < 1; r++) {
            const float4 h = h4[tid];
            const int st = tid >> 4, c = (tid & 15) * 4;
            h8[st][c] = h.x; h8[st][c + 1] = h.y;
            h8[st][c + 2] = h.z; h8[st][c + 3] = h.w;
        }
    }
    __syncthreads();

#pragma unroll
    for (int o = 0; o < 4; o++) {
        const int idx = tid + 128 * o;       // 0..511
        const int st = idx >> 6, e = idx & 63;
        float acc = 0.0f;
#pragma unroll
        for (int d = 0; d < 64; d++) acc += win[e][d] * h8[st][d];
        g_proj[(size_t)(bs0 + st) * 64 + e] = acc;
    }
}

// ---------------------------------------------------------------------------
// Kernel 3: decoder on HMMA. Block = 8 steps; per chunk (1 step): A = noise
// [50+14 pad][64 hi|64 lo] bf16, B = precomputed W planes (cp.async, resident).
// LDG(chunk c+1) overlaps MMA(chunk c). Epilogue from fragments:
// mean_out[bs] = mean_n softplus( sum_e relu(z[n][e] + proj[bs][e]) * wev[e] ).
// ---------------------------------------------------------------------------
__global__ __launch_bounds__(128) void decoder_hmma_kernel(
    const float* __restrict__ noise,
    const float* __restrict__ W_event,
    float* __restrict__ mean_out) {
    __shared__ __align__(16) __nv_bfloat16 A_s[64][136];   // 17.4 KB
    __shared__ __align__(16) __nv_bfloat16 B_s[64][136];   // 17.4 KB
    __shared__ float pj_s[8][64];                          // 2 KB
    __shared__ float wev_s[64], srow[64];

    const int tid  = threadIdx.x;
    const int lane = tid & 31;
    const int wid  = tid >> 5;
    const int b  = blockIdx.x >> 8;
    const int s0 = (blockIdx.x & 255) * 8;
    const int bs0 = b * SS + s0;

    // prologue: W planes + proj via cp.async; wev; zero A pad rows
    {
        const char* wsrc = (const char*)g_wplanes;
        char* wdst = (char*)A_s;  // temp? no — straight into B_s
        (void)wdst;
#pragma unroll
        for (int r = 0; r < 9; r++) {
            const int idx = tid + 128 * r;     // 0..1087 (17408 B / 16)
            if (idx < 1088) cp16((char*)B_s + idx * 16, wsrc + idx * 16);
        }
        cp16(&pj_s[0][0] + tid * 4, g_proj + (size_t)bs0 * 64 + tid * 4);
        cp_commit();
        if (tid < 64) wev_s[tid] = W_event[tid];
        for (int i = tid; i < 14 * 68; i += 128)   // rows 50..63, u32 granules
            ((u32*)&A_s[50][0])[i] = 0u;
    }

    // load chunk 0 noise into regs
    float4 nreg[7];
    {
        const float4* src = (const float4*)(noise + (size_t)bs0 * NSAMP * 64);
#pragma unroll
        for (int r = 0; r < 7; r++) {
            const int idx = tid + 128 * r;
            if (idx < 800) nreg[r] = __ldg(src + idx);
        }
    }
    cp_wait0();
    __syncthreads();

    const u32 Abase = smem_u32(A_s);
    const u32 Bbase = smem_u32(B_s);
    const int arow = 16 * wid + (lane & 15);
    const int acol = (lane >> 4) * 8;
    const int bk = (lane & 7) + 8 * ((lane >> 3) & 1);
    const int bn = 8 * (lane >> 4);

    for (int c = 0; c < 8; c++) {
        // STS chunk c (convert to hi|lo planes)
#pragma unroll
        for (int r = 0; r < 7; r++) {
            const int idx = tid + 128 * r;
            if (idx < 800) {
                const int row = idx >> 4, c4 = (idx & 15) * 4;
                *(uint2*)&A_s[row][c4]      = bf16x4_hi(nreg[r]);
                *(uint2*)&A_s[row][64 + c4] = bf16x4_lo(nreg[r]);
            }
        }
        __syncthreads();

        // prefetch chunk c+1
        if (c < 7) {
            const float4* src =
                (const float4*)(noise + (size_t)(bs0 + c + 1) * NSAMP * 64);
#pragma unroll
            for (int r = 0; r < 7; r++) {
                const int idx = tid + 128 * r;
                if (idx < 800) nreg[r] = __ldg(src + idx);
            }
        }

        // MMA: 3 passes
        float acc[8][4];
#pragma unroll
        for (int n = 0; n < 8; n++)
#pragma unroll
            for (int i = 0; i < 4; i++) acc[n][i] = 0.0f;
#pragma unroll
        for (int pass = 0; pass < 3; pass++) {
            const int pa = (pass == 2) ? 64 : 0;
            const int pb = (pass == 1) ? 64 : 0;
#pragma unroll
            for (int ks = 0; ks < 4; ks++) {
                u32 a[4];
                LDSM_X4(a, Abase + (u32)(arow * 272 + (pa + ks * 16 + acol) * 2));
#pragma unroll
                for (int ntp = 0; ntp < 4; ntp++) {
                    u32 bb[4];
                    LDSM_X4T(bb, Bbase + (u32)((ks * 16 + bk) * 272
                                               + (pb + ntp * 16 + bn) * 2));
                    MMA16816(acc[2 * ntp],     a, bb[0], bb[1]);
                    MMA16816(acc[2 * ntp + 1], a, bb[2], bb[3]);
                }
            }
        }

        // epilogue: per-row g = sum_e relu(z+pj)*wev; quad reduce
#pragma unroll
        for (int h = 0; h < 2; h++) {
            const int row = 16 * wid + (lane >> 2) + 8 * h;
            float g = 0.0f;
#pragma unroll
            for (int nt = 0; nt < 8; nt++) {
#pragma unroll
                for (int j = 0; j < 2; j++) {
                    const int e = nt * 8 + (lane & 3) * 2 + j;
                    const float z = acc[nt][2 * h + j] + pj_s[c][e];
                    g = fmaf(fmaxf(z, 0.0f), wev_s[e], g);
                }
            }
            g += __shfl_xor_sync(0xffffffffu, g, 1);
            g += __shfl_xor_sync(0xffffffffu, g, 2);
            if ((lane & 3) == 0 && row < NSAMP) srow[row] = softplusf(g);
        }
        __syncthreads();

        if (wid == 0) {
            float t = (lane < 25) ? srow[lane] + srow[lane + 25] : 0.0f;
#pragma unroll
            for (int o = 16; o > 0; o >>= 1)
                t += __shfl_xor_sync(0xffffffffu, t, o);
            if (lane == 0) mean_out[bs0 + c] = t * (1.0f / NSAMP);
        }
    }
}

// ---------------------------------------------------------------------------
extern "C" void kernel_launch(void* const* d_in, const int* in_sizes, int n_in,
                              void* d_out, int out_size) {
    const int*   event_type = (const int*)d_in[0];
    const float* event_time = (const float*)d_in[1];
    const float* noise      = (const float*)d_in[3];
    const float* Wt_pos     = (const float*)d_in[4];
    const float* type_table = (const float*)d_in[5];
    const float* gamma      = (const float*)d_in[6];
    const float* beta       = (const float*)d_in[7];
    const float* W_in       = (const float*)d_in[8];
    const float* W_noise    = (const float*)d_in[9];
    const float* W_event    = (const float*)d_in[10];

    float* out        = (float*)d_out;
    float* mean_out   = out;               // [B,S]
    float* hidden_out = out + BB * SS;     // [B,S,D]

    pe_kernel<<<(BB * SS * 32 + 255) / 256, 256>>>(event_type, event_time,
                                                   Wt_pos, type_table);
    prep_w_kernel<<<32, 128>>>(W_noise);
    hidden_hmma_kernel<<<dim3(32, BB), 128>>>(event_time, gamma, beta, hidden_out);
    proj_kernel<<<BB * SS / 8, 128>>>(W_in, hidden_out);
    decoder_hmma_kernel<<<BB * SS / 8, 128>>>(noise, W_event, mean_out);
}

// round 11
// speedup vs baseline: 2.5102x; 1.0419x over previous
#include <cuda_runtime.h>
#include <cuda_bf16.h>
#include <cstdint>

#define BB 8
#define SS 2048
#define DD 64
#define NSAMP 50

typedef unsigned long long u64;
typedef unsigned int u32;

__device__ __nv_bfloat16 g_peh[BB * SS * DD];   // pe hi plane (2 MB)
__device__ __nv_bfloat16 g_pel[BB * SS * DD];   // pe lo plane (2 MB)
__device__ float g_emb[BB * SS];                // 64 KB
__device__ __nv_bfloat16 g_wplanes[64 * 136];   // W_noise^T bf16 hi|lo (B_s layout)
__device__ __nv_bfloat16 g_winplanes[64 * 136]; // W_in^T  bf16 hi|lo (B_s layout)
__device__ float g_proj[BB * SS * DD];          // proj = hidden @ W_in^T (4 MB)

// ---- misc helpers -----------------------------------------------------------
__device__ __forceinline__ float softplusf(float x) {
    return fmaxf(x, 0.0f) + log1pf(expf(-fabsf(x)));
}
__device__ __forceinline__ void cp16(void* dst, const void* src) {
    unsigned sa = (unsigned)__cvta_generic_to_shared(dst);
    asm volatile("cp.async.ca.shared.global [%0],[%1],16;" :: "r"(sa), "l"(src));
}
__device__ __forceinline__ void cp4(void* dst, const void* src) {
    unsigned sa = (unsigned)__cvta_generic_to_shared(dst);
    asm volatile("cp.async.ca.shared.global [%0],[%1],4;" :: "r"(sa), "l"(src));
}
__device__ __forceinline__ void cp_commit() { asm volatile("cp.async.commit_group;"); }
__device__ __forceinline__ void cp_wait0()  { asm volatile("cp.async.wait_group 0;"); }

// ---- HMMA helpers (sm_80+ PTX) -----------------------------------------------
__device__ __forceinline__ u32 smem_u32(const void* p) {
    return (u32)__cvta_generic_to_shared(p);
}
#define LDSM_X4(r, a) \
    asm volatile("ldmatrix.sync.aligned.m8n8.x4.shared.b16 {%0,%1,%2,%3},[%4];" \
        : "=r"((r)[0]), "=r"((r)[1]), "=r"((r)[2]), "=r"((r)[3]) : "r"(a))
#define LDSM_X4T(r, a) \
    asm volatile("ldmatrix.sync.aligned.m8n8.x4.trans.shared.b16 {%0,%1,%2,%3},[%4];" \
        : "=r"((r)[0]), "=r"((r)[1]), "=r"((r)[2]), "=r"((r)[3]) : "r"(a))
#define MMA16816(c, a, b0, b1) \
    asm volatile("mma.sync.aligned.m16n8k16.row.col.f32.bf16.bf16.f32 " \
        "{%0,%1,%2,%3},{%4,%5,%6,%7},{%8,%9},{%0,%1,%2,%3};" \
        : "+f"((c)[0]), "+f"((c)[1]), "+f"((c)[2]), "+f"((c)[3]) \
        : "r"((a)[0]), "r"((a)[1]), "r"((a)[2]), "r"((a)[3]), "r"(b0), "r"(b1))

__device__ __forceinline__ uint2 bf16x4_hi(float4 v) {
    __nv_bfloat162 a = __floats2bfloat162_rn(v.x, v.y);
    __nv_bfloat162 b = __floats2bfloat162_rn(v.z, v.w);
    uint2 r; r.x = *(u32*)&a; r.y = *(u32*)&b; return r;
}
__device__ __forceinline__ uint2 bf16x4_lo(float4 v) {
    float hx = __bfloat162float(__float2bfloat16(v.x));
    float hy = __bfloat162float(__float2bfloat16(v.y));
    float hz = __bfloat162float(__float2bfloat16(v.z));
    float hw = __bfloat162float(__float2bfloat16(v.w));
    __nv_bfloat162 a = __floats2bfloat162_rn(v.x - hx, v.y - hy);
    __nv_bfloat162 b = __floats2bfloat162_rn(v.z - hz, v.w - hw);
    uint2 r; r.x = *(u32*)&a; r.y = *(u32*)&b; return r;
}

// ---------------------------------------------------------------------------
// Kernel 1: pe (bf16 hi/lo planes) + type embedding scalar
// ---------------------------------------------------------------------------
__global__ void pe_kernel(const int* __restrict__ etype,
                          const float* __restrict__ etime,
                          const float* __restrict__ Wt_pos,
                          const float* __restrict__ type_table) {
    int idx = blockIdx.x * blockDim.x + threadIdx.x;
    if (idx >= BB * SS * 32) return;
    int k = idx & 31;
    int s = (idx >> 5) & (SS - 1);
    int b = idx >> 16;
    int bs = b * SS + s;
    float t = etime[bs];
    float div = expf((float)(2 * k) * -0.14391156831212787f);
    float a = (float)s * div + t * Wt_pos[k];
    float sv, cv;
    __sincosf(a, &sv, &cv);
    __nv_bfloat16 sh = __float2bfloat16(sv);
    __nv_bfloat16 ch = __float2bfloat16(cv);
    g_peh[bs * DD + k]      = sh;
    g_pel[bs * DD + k]      = __float2bfloat16(sv - __bfloat162float(sh));
    g_peh[bs * DD + 32 + k] = ch;
    g_pel[bs * DD + 32 + k] = __float2bfloat16(cv - __bfloat162float(ch));
    if (k == 0) {
        int ty = etype[bs];
        g_emb[bs] = (ty == 0) ? 0.0f : type_table[ty] * 8.0f;
    }
}

// ---------------------------------------------------------------------------
// Kernel 1b: W_noise and W_in -> bf16 hi|lo planes in B_s[64][136] layout.
// planes[d][e] = hi(W[e][d]); planes[d][64+e] = lo.
// ---------------------------------------------------------------------------
__global__ void prep_w_kernel(const float* __restrict__ W_noise,
                              const float* __restrict__ W_in) {
    int idx = blockIdx.x * blockDim.x + threadIdx.x;
    if (idx >= 4096) return;
    int e = idx >> 6, d = idx & 63;
    {
        float v = W_noise[idx];
        __nv_bfloat16 hi = __float2bfloat16(v);
        g_wplanes[d * 136 + e]      = hi;
        g_wplanes[d * 136 + 64 + e] = __float2bfloat16(v - __bfloat162float(hi));
    }
    {
        float v = W_in[idx];
        __nv_bfloat16 hi = __float2bfloat16(v);
        g_winplanes[d * 136 + e]      = hi;
        g_winplanes[d * 136 + 64 + e] = __float2bfloat16(v - __bfloat162float(hi));
    }
}

// ---------------------------------------------------------------------------
// Kernel 2: hidden = causal(scores) @ pe on HMMA, fused LayerNorm,
// then proj = hidden @ W_in^T as one extra HMMA tile (writes g_proj).
// ---------------------------------------------------------------------------
__global__ __launch_bounds__(128) void hidden_hmma_kernel(
    const float* __restrict__ etime,
    const float* __restrict__ gamma,
    const float* __restrict__ beta,
    float* __restrict__ hidden_out) {
    __shared__ __align__(16) __nv_bfloat16 A_s[64][136];
    __shared__ __align__(16) __nv_bfloat16 B_s[64][136];
    __shared__ float ti_s[64], ei_s[64];
    __shared__ float tj_s[2][64], ej_s[2][64];
    __shared__ float gm_s[64], bt_s[64];

    const int b   = blockIdx.y;
    const int T   = 31 - blockIdx.x;
    const int tid = threadIdx.x;
    const int lane = tid & 31;
    const int wid  = tid >> 5;

    const float* etb = etime + b * SS;
    const float* emb = g_emb + b * SS;
    const __nv_bfloat16* peh = g_peh + (size_t)b * SS * DD;
    const __nv_bfloat16* pel = g_pel + (size_t)b * SS * DD;

    if (tid < 64) {
        ti_s[tid] = etb[T * 64 + tid];
        gm_s[tid] = gamma[tid];
        tj_s[0][tid] = etb[tid];
        ej_s[0][tid] = emb[tid];
    } else {
        ei_s[tid - 64] = emb[T * 64 + tid - 64];
        bt_s[tid - 64] = beta[tid - 64];
    }

    float acc[8][4];
#pragma unroll
    for (int n = 0; n < 8; n++)
#pragma unroll
        for (int i = 0; i < 4; i++) acc[n][i] = 0.0f;

    const u32 Abase = smem_u32(A_s);
    const u32 Bbase = smem_u32(B_s);
    const int arow = 16 * wid + (lane & 15);
    const int acol = (lane >> 4) * 8;
    const int bk = (lane & 7) + 8 * ((lane >> 3) & 1);
    const int bn = 8 * (lane >> 4);
    const int srow = tid >> 1;
    const int sjh  = (tid & 1) * 32;
    const int iglob = T * 64 + srow;

    __syncthreads();

    for (int jt = 0; jt <= T; jt++) {
        const int buf = jt & 1;
        const int j0 = jt * 64;
        {
#pragma unroll
            for (int r = 0; r < 8; r++) {
                const int idx = tid + 128 * r;
                const int row = idx >> 4;
                const int pl  = (idx >> 3) & 1;
                const int c   = idx & 7;
                const __nv_bfloat16* src = pl ? pel : peh;
                cp16(&B_s[row][pl * 64 + c * 8], src + (j0 + row) * DD + c * 8);
            }
            if (jt < T) {
                const int nb = buf ^ 1;
                if (tid < 64) cp4(&tj_s[nb][tid], etb + j0 + 64 + tid);
                else          cp4(&ej_s[nb][tid - 64], emb + j0 + 64 + tid - 64);
            }
            cp_commit();
        }
        {
            const float tii = ti_s[srow];
            const float eii = ei_s[srow];
#pragma unroll 4
            for (int q = 0; q < 16; q++) {
                float sc[2];
#pragma unroll
                for (int j = 0; j < 2; j++) {
                    const int jj = sjh + 2 * q + j;
                    const float td = tii - tj_s[buf][jj];
                    const float ae = fabsf(eii - ej_s[buf][jj]);
                    const float prod = (1.0f + 0.5f * td * td) * (1.0f + __expf(ae));
                    sc[j] = (j0 + jj <= iglob) ? __fdividef(1.0f, prod) : 0.0f;
                }
                const __nv_bfloat162 hi2 = __floats2bfloat162_rn(sc[0], sc[1]);
                const float r0 = sc[0] - __bfloat162float(__low2bfloat16(hi2));
                const float r1 = sc[1] - __bfloat162float(__high2bfloat16(hi2));
                const __nv_bfloat162 lo2 = __floats2bfloat162_rn(r0, r1);
                *(u32*)&A_s[srow][sjh + 2 * q]      = *(const u32*)&hi2;
                *(u32*)&A_s[srow][64 + sjh + 2 * q] = *(const u32*)&lo2;
            }
        }
        cp_wait0();
        __syncthreads();

#pragma unroll
        for (int pass = 0; pass < 3; pass++) {
            const int pa = (pass == 2) ? 64 : 0;
            const int pb = (pass == 1) ? 64 : 0;
#pragma unroll
            for (int ks = 0; ks < 4; ks++) {
                u32 a[4];
                LDSM_X4(a, Abase + (u32)(arow * 272 + (pa + ks * 16 + acol) * 2));
#pragma unroll
                for (int ntp = 0; ntp < 4; ntp++) {
                    u32 bb[4];
                    LDSM_X4T(bb, Bbase + (u32)((ks * 16 + bk) * 272
                                               + (pb + ntp * 16 + bn) * 2));
                    MMA16816(acc[2 * ntp],     a, bb[0], bb[1]);
                    MMA16816(acc[2 * ntp + 1], a, bb[2], bb[3]);
                }
            }
        }
        __syncthreads();
    }

    // prefetch W_in planes into B_s (free after last sync) for the proj MMA
    {
#pragma unroll
        for (int r = 0; r < 9; r++) {
            const int idx = tid + 128 * r;
            if (idx < 1088) cp16((char*)B_s + idx * 16, (const char*)g_winplanes + idx * 16);
        }
        cp_commit();
    }

    // ---- fused LayerNorm epilogue; also deposits hidden bf16 hi|lo into A_s
#pragma unroll
    for (int h = 0; h < 2; h++) {
        const int row = 16 * wid + (lane >> 2) + 8 * h;
        float sum = 0.0f, sq = 0.0f;
#pragma unroll
        for (int nt = 0; nt < 8; nt++) {
#pragma unroll
            for (int j = 0; j < 2; j++) {
                const float v = acc[nt][2 * h + j];
                sum += v; sq += v * v;
            }
        }
        sum += __shfl_xor_sync(0xffffffffu, sum, 1);
        sq  += __shfl_xor_sync(0xffffffffu, sq,  1);
        sum += __shfl_xor_sync(0xffffffffu, sum, 2);
        sq  += __shfl_xor_sync(0xffffffffu, sq,  2);
        const float mu  = sum * (1.0f / 64.0f);
        const float var = sq * (1.0f / 64.0f) - mu * mu;
        const float inv = rsqrtf(var + 1e-6f);
        float* outp = hidden_out + ((size_t)(b * SS + T * 64 + row)) * 64;
#pragma unroll
        for (int nt = 0; nt < 8; nt++) {
            const int d0 = nt * 8 + (lane & 3) * 2;
            float2 o;
            o.x = (acc[nt][2 * h]     - mu) * inv * gm_s[d0]     + bt_s[d0];
            o.y = (acc[nt][2 * h + 1] - mu) * inv * gm_s[d0 + 1] + bt_s[d0 + 1];
            *(float2*)(outp + d0) = o;
            // deposit bf16 hi|lo planes for the proj MMA
            const __nv_bfloat162 hi2 = __floats2bfloat162_rn(o.x, o.y);
            const float r0 = o.x - __bfloat162float(__low2bfloat16(hi2));
            const float r1 = o.y - __bfloat162float(__high2bfloat16(hi2));
            const __nv_bfloat162 lo2 = __floats2bfloat162_rn(r0, r1);
            *(u32*)&A_s[row][d0]      = *(const u32*)&hi2;
            *(u32*)&A_s[row][64 + d0] = *(const u32*)&lo2;
        }
    }
    cp_wait0();
    __syncthreads();

    // ---- proj MMA: proj = hidden @ W_in^T (3-pass bf16 split) ----
#pragma unroll
    for (int n = 0; n < 8; n++)
#pragma unroll
        for (int i = 0; i < 4; i++) acc[n][i] = 0.0f;
#pragma unroll
    for (int pass = 0; pass < 3; pass++) {
        const int pa = (pass == 2) ? 64 : 0;
        const int pb = (pass == 1) ? 64 : 0;
#pragma unroll
        for (int ks = 0; ks < 4; ks++) {
            u32 a[4];
            LDSM_X4(a, Abase + (u32)(arow * 272 + (pa + ks * 16 + acol) * 2));
#pragma unroll
            for (int ntp = 0; ntp < 4; ntp++) {
                u32 bb[4];
                LDSM_X4T(bb, Bbase + (u32)((ks * 16 + bk) * 272
                                           + (pb + ntp * 16 + bn) * 2));
                MMA16816(acc[2 * ntp],     a, bb[0], bb[1]);
                MMA16816(acc[2 * ntp + 1], a, bb[2], bb[3]);
            }
        }
    }
#pragma unroll
    for (int h = 0; h < 2; h++) {
        const int row = 16 * wid + (lane >> 2) + 8 * h;
        float* outp = g_proj + ((size_t)(b * SS + T * 64 + row)) * 64;
#pragma unroll
        for (int nt = 0; nt < 8; nt++) {
            const int d0 = nt * 8 + (lane & 3) * 2;
            float2 o;
            o.x = acc[nt][2 * h];
            o.y = acc[nt][2 * h + 1];
            *(float2*)(outp + d0) = o;
        }
    }
}

// ---------------------------------------------------------------------------
// Kernel 3: decoder on HMMA (unchanged from R8, passing).
// ---------------------------------------------------------------------------
__global__ __launch_bounds__(128) void decoder_hmma_kernel(
    const float* __restrict__ noise,
    const float* __restrict__ W_event,
    float* __restrict__ mean_out) {
    __shared__ __align__(16) __nv_bfloat16 A_s[64][136];
    __shared__ __align__(16) __nv_bfloat16 B_s[64][136];
    __shared__ float pj_s[8][64];
    __shared__ float wev_s[64], srow[64];

    const int tid  = threadIdx.x;
    const int lane = tid & 31;
    const int wid  = tid >> 5;
    const int b  = blockIdx.x >> 8;
    const int s0 = (blockIdx.x & 255) * 8;
    const int bs0 = b * SS + s0;

    {
        const char* wsrc = (const char*)g_wplanes;
#pragma unroll
        for (int r = 0; r < 9; r++) {
            const int idx = tid + 128 * r;
            if (idx < 1088) cp16((char*)B_s + idx * 16, wsrc + idx * 16);
        }
        cp16(&pj_s[0][0] + tid * 4, g_proj + (size_t)bs0 * 64 + tid * 4);
        cp_commit();
        if (tid < 64) wev_s[tid] = W_event[tid];
        for (int i = tid; i < 14 * 68; i += 128)
            ((u32*)&A_s[50][0])[i] = 0u;
    }

    float4 nreg[7];
    {
        const float4* src = (const float4*)(noise + (size_t)bs0 * NSAMP * 64);
#pragma unroll
        for (int r = 0; r < 7; r++) {
            const int idx = tid + 128 * r;
            if (idx < 800) nreg[r] = __ldg(src + idx);
        }
    }
    cp_wait0();
    __syncthreads();

    const u32 Abase = smem_u32(A_s);
    const u32 Bbase = smem_u32(B_s);
    const int arow = 16 * wid + (lane & 15);
    const int acol = (lane >> 4) * 8;
    const int bk = (lane & 7) + 8 * ((lane >> 3) & 1);
    const int bn = 8 * (lane >> 4);

    for (int c = 0; c < 8; c++) {
#pragma unroll
        for (int r = 0; r < 7; r++) {
            const int idx = tid + 128 * r;
            if (idx < 800) {
                const int row = idx >> 4, c4 = (idx & 15) * 4;
                *(uint2*)&A_s[row][c4]      = bf16x4_hi(nreg[r]);
                *(uint2*)&A_s[row][64 + c4] = bf16x4_lo(nreg[r]);
            }
        }
        __syncthreads();

        if (c < 7) {
            const float4* src =
                (const float4*)(noise + (size_t)(bs0 + c + 1) * NSAMP * 64);
#pragma unroll
            for (int r = 0; r < 7; r++) {
                const int idx = tid + 128 * r;
                if (idx < 800) nreg[r] = __ldg(src + idx);
            }
        }

        float acc[8][4];
#pragma unroll
        for (int n = 0; n < 8; n++)
#pragma unroll
            for (int i = 0; i < 4; i++) acc[n][i] = 0.0f;
#pragma unroll
        for (int pass = 0; pass < 3; pass++) {
            const int pa = (pass == 2) ? 64 : 0;
            const int pb = (pass == 1) ? 64 : 0;
#pragma unroll
            for (int ks = 0; ks < 4; ks++) {
                u32 a[4];
                LDSM_X4(a, Abase + (u32)(arow * 272 + (pa + ks * 16 + acol) * 2));
#pragma unroll
                for (int ntp = 0; ntp < 4; ntp++) {
                    u32 bb[4];
                    LDSM_X4T(bb, Bbase + (u32)((ks * 16 + bk) * 272
                                               + (pb + ntp * 16 + bn) * 2));
                    MMA16816(acc[2 * ntp],     a, bb[0], bb[1]);
                    MMA16816(acc[2 * ntp + 1], a, bb[2], bb[3]);
                }
            }
        }

#pragma unroll
        for (int h = 0; h < 2; h++) {
            const int row = 16 * wid + (lane >> 2) + 8 * h;
            float g = 0.0f;
#pragma unroll
            for (int nt = 0; nt < 8; nt++) {
#pragma unroll
                for (int j = 0; j < 2; j++) {
                    const int e = nt * 8 + (lane & 3) * 2 + j;
                    const float z = acc[nt][2 * h + j] + pj_s[c][e];
                    g = fmaf(fmaxf(z, 0.0f), wev_s[e], g);
                }
            }
            g += __shfl_xor_sync(0xffffffffu, g, 1);
            g += __shfl_xor_sync(0xffffffffu, g, 2);
            if ((lane & 3) == 0 && row < NSAMP) srow[row] = softplusf(g);
        }
        __syncthreads();

        if (wid == 0) {
            float t = (lane < 25) ? srow[lane] + srow[lane + 25] : 0.0f;
#pragma unroll
            for (int o = 16; o > 0; o >>= 1)
                t += __shfl_xor_sync(0xffffffffu, t, o);
            if (lane == 0) mean_out[bs0 + c] = t * (1.0f / NSAMP);
        }
    }
}

// ---------------------------------------------------------------------------
extern "C" void kernel_launch(void* const* d_in, const int* in_sizes, int n_in,
                              void* d_out, int out_size) {
    const int*   event_type = (const int*)d_in[0];
    const float* event_time = (const float*)d_in[1];
    const float* noise      = (const float*)d_in[3];
    const float* Wt_pos     = (const float*)d_in[4];
    const float* type_table = (const float*)d_in[5];
    const float* gamma      = (const float*)d_in[6];
    const float* beta       = (const float*)d_in[7];
    const float* W_in       = (const float*)d_in[8];
    const float* W_noise    = (const float*)d_in[9];
    const float* W_event    = (const float*)d_in[10];

    float* out        = (float*)d_out;
    float* mean_out   = out;               // [B,S]
    float* hidden_out = out + BB * SS;     // [B,S,D]

    pe_kernel<<<(BB * SS * 32 + 255) / 256, 256>>>(event_type, event_time,
                                                   Wt_pos, type_table);
    prep_w_kernel<<<32, 128>>>(W_noise, W_in);
    hidden_hmma_kernel<<<dim3(32, BB), 128>>>(event_time, gamma, beta, hidden_out);
    decoder_hmma_kernel<<<BB * SS / 8, 128>>>(noise, W_event, mean_out);
}

// round 12
// speedup vs baseline: 3.6367x; 1.4488x over previous
#include <cuda_runtime.h>
#include <cuda_bf16.h>
#include <cstdint>

#define BB 8
#define SS 2048
#define DD 64
#define NSAMP 50
#define NTY 11

typedef unsigned long long u64;
typedef unsigned int u32;

__device__ __nv_bfloat16 g_peh[BB * SS * DD];   // pe hi plane (2 MB)
__device__ __nv_bfloat16 g_pel[BB * SS * DD];   // pe lo plane (2 MB)
__device__ __nv_bfloat16 g_wplanes[64 * 136];   // W_noise^T bf16 hi|lo (B_s layout)
__device__ __nv_bfloat16 g_winplanes[64 * 136]; // W_in^T  bf16 hi|lo (B_s layout)
__device__ float g_proj[BB * SS * DD];          // proj = hidden @ W_in^T (4 MB)
__device__ float g_gate[NTY * NTY];             // sigmoid(-|emb_a - emb_b|) LUT

// ---- misc helpers -----------------------------------------------------------
__device__ __forceinline__ float softplusf(float x) {
    return fmaxf(x, 0.0f) + log1pf(expf(-fabsf(x)));
}
__device__ __forceinline__ void cp16(void* dst, const void* src) {
    unsigned sa = (unsigned)__cvta_generic_to_shared(dst);
    asm volatile("cp.async.ca.shared.global [%0],[%1],16;" :: "r"(sa), "l"(src));
}
__device__ __forceinline__ void cp4(void* dst, const void* src) {
    unsigned sa = (unsigned)__cvta_generic_to_shared(dst);
    asm volatile("cp.async.ca.shared.global [%0],[%1],4;" :: "r"(sa), "l"(src));
}
__device__ __forceinline__ void cp_commit() { asm volatile("cp.async.commit_group;"); }
__device__ __forceinline__ void cp_wait0()  { asm volatile("cp.async.wait_group 0;"); }

// ---- HMMA helpers (sm_80+ PTX) -----------------------------------------------
__device__ __forceinline__ u32 smem_u32(const void* p) {
    return (u32)__cvta_generic_to_shared(p);
}
#define LDSM_X4(r, a) \
    asm volatile("ldmatrix.sync.aligned.m8n8.x4.shared.b16 {%0,%1,%2,%3},[%4];" \
        : "=r"((r)[0]), "=r"((r)[1]), "=r"((r)[2]), "=r"((r)[3]) : "r"(a))
#define LDSM_X4T(r, a) \
    asm volatile("ldmatrix.sync.aligned.m8n8.x4.trans.shared.b16 {%0,%1,%2,%3},[%4];" \
        : "=r"((r)[0]), "=r"((r)[1]), "=r"((r)[2]), "=r"((r)[3]) : "r"(a))
#define MMA16816(c, a0, a1, a2, a3, b0, b1) \
    asm volatile("mma.sync.aligned.m16n8k16.row.col.f32.bf16.bf16.f32 " \
        "{%0,%1,%2,%3},{%4,%5,%6,%7},{%8,%9},{%0,%1,%2,%3};" \
        : "+f"((c)[0]), "+f"((c)[1]), "+f"((c)[2]), "+f"((c)[3]) \
        : "r"(a0), "r"(a1), "r"(a2), "r"(a3), "r"(b0), "r"(b1))

__device__ __forceinline__ uint2 bf16x4_hi(float4 v) {
    __nv_bfloat162 a = __floats2bfloat162_rn(v.x, v.y);
    __nv_bfloat162 b = __floats2bfloat162_rn(v.z, v.w);
    uint2 r; r.x = *(u32*)&a; r.y = *(u32*)&b; return r;
}
__device__ __forceinline__ uint2 bf16x4_lo(float4 v) {
    float hx = __bfloat162float(__float2bfloat16(v.x));
    float hy = __bfloat162float(__float2bfloat16(v.y));
    float hz = __bfloat162float(__float2bfloat16(v.z));
    float hw = __bfloat162float(__float2bfloat16(v.w));
    __nv_bfloat162 a = __floats2bfloat162_rn(v.x - hx, v.y - hy);
    __nv_bfloat162 b = __floats2bfloat162_rn(v.z - hz, v.w - hw);
    uint2 r; r.x = *(u32*)&a; r.y = *(u32*)&b; return r;
}

// ---------------------------------------------------------------------------
// Kernel 1: pe bf16 hi/lo planes
// ---------------------------------------------------------------------------
__global__ void pe_kernel(const float* __restrict__ etime,
                          const float* __restrict__ Wt_pos) {
    int idx = blockIdx.x * blockDim.x + threadIdx.x;
    if (idx >= BB * SS * 32) return;
    int k = idx & 31;
    int s = (idx >> 5) & (SS - 1);
    int b = idx >> 16;
    int bs = b * SS + s;
    float t = etime[bs];
    float div = expf((float)(2 * k) * -0.14391156831212787f);
    float a = (float)s * div + t * Wt_pos[k];
    float sv, cv;
    __sincosf(a, &sv, &cv);
    __nv_bfloat16 sh = __float2bfloat16(sv);
    __nv_bfloat16 ch = __float2bfloat16(cv);
    g_peh[bs * DD + k]      = sh;
    g_pel[bs * DD + k]      = __float2bfloat16(sv - __bfloat162float(sh));
    g_peh[bs * DD + 32 + k] = ch;
    g_pel[bs * DD + 32 + k] = __float2bfloat16(cv - __bfloat162float(ch));
}

// ---------------------------------------------------------------------------
// Kernel 1b: W planes (ldmatrix layout) + type-pair gate LUT
// ---------------------------------------------------------------------------
__global__ void prep_w_kernel(const float* __restrict__ W_noise,
                              const float* __restrict__ W_in,
                              const float* __restrict__ type_table) {
    int idx = blockIdx.x * blockDim.x + threadIdx.x;
    if (idx < NTY * NTY) {
        int a = idx / NTY, c = idx % NTY;
        float ea = (a == 0) ? 0.0f : type_table[a] * 8.0f;
        float ec = (c == 0) ? 0.0f : type_table[c] * 8.0f;
        g_gate[idx] = 1.0f / (1.0f + expf(fabsf(ea - ec)));
    }
    if (idx >= 4096) return;
    int e = idx >> 6, d = idx & 63;
    {
        float v = W_noise[idx];
        __nv_bfloat16 hi = __float2bfloat16(v);
        g_wplanes[d * 136 + e]      = hi;
        g_wplanes[d * 136 + 64 + e] = __float2bfloat16(v - __bfloat162float(hi));
    }
    {
        float v = W_in[idx];
        __nv_bfloat16 hi = __float2bfloat16(v);
        g_winplanes[d * 136 + e]      = hi;
        g_winplanes[d * 136 + 64 + e] = __float2bfloat16(v - __bfloat162float(hi));
    }
}

// ---------------------------------------------------------------------------
// Kernel 2: hidden (HMMA) + LayerNorm + proj MMA.  256 threads:
// warp w: row group wid4=w&3 (16 rows), col half whalf=w>>2 (32 cols).
// ---------------------------------------------------------------------------
__global__ __launch_bounds__(256) void hidden_hmma_kernel(
    const float* __restrict__ etime,
    const int*   __restrict__ etype,
    const float* __restrict__ gamma,
    const float* __restrict__ beta,
    float* __restrict__ hidden_out) {
    __shared__ __align__(16) __nv_bfloat16 A_s[64][136];
    __shared__ __align__(16) __nv_bfloat16 B_s[64][136];
    __shared__ float ti_s[64];
    __shared__ int   tyi_s[64];
    __shared__ float tj_s[2][64];
    __shared__ int   tyj_s[2][64];
    __shared__ float gm_s[64], bt_s[64];
    __shared__ float gate_s[NTY * NTY];
    __shared__ float psum_s[2][64], psq_s[2][64];

    const int b   = blockIdx.y;
    const int T   = 31 - blockIdx.x;
    const int tid = threadIdx.x;
    const int lane = tid & 31;
    const int wid  = tid >> 5;
    const int wid4 = wid & 3;
    const int whalf = wid >> 2;

    const float* etb = etime + b * SS;
    const int*   tyb = etype + b * SS;
    const __nv_bfloat16* peh = g_peh + (size_t)b * SS * DD;
    const __nv_bfloat16* pel = g_pel + (size_t)b * SS * DD;

    if (tid < 64) {
        ti_s[tid]  = etb[T * 64 + tid];
        tyi_s[tid] = tyb[T * 64 + tid];
        tj_s[0][tid]  = etb[tid];
        tyj_s[0][tid] = tyb[tid];
        gm_s[tid] = gamma[tid];
        bt_s[tid] = beta[tid];
    } else if (tid < 64 + NTY * NTY) {
        gate_s[tid - 64] = g_gate[tid - 64];
    }

    float acc[4][4];
#pragma unroll
    for (int n = 0; n < 4; n++)
#pragma unroll
        for (int i = 0; i < 4; i++) acc[n][i] = 0.0f;

    const u32 Abase = smem_u32(A_s);
    const u32 Bbase = smem_u32(B_s);
    const int arow = 16 * wid4 + (lane & 15);
    const int acol = (lane >> 4) * 8;
    const int bk = (lane & 7) + 8 * ((lane >> 3) & 1);
    const int bn = 8 * (lane >> 4);
    const int srow = tid >> 2;          // score row 0..63
    const int sjh  = (tid & 3) * 16;    // 16 evals per thread
    const int iglob = T * 64 + srow;

    __syncthreads();

    for (int jt = 0; jt <= T; jt++) {
        const int buf = jt & 1;
        const int j0 = jt * 64;
        {
#pragma unroll
            for (int r = 0; r < 4; r++) {
                const int idx = tid + 256 * r;       // 0..1023
                const int row = idx >> 4;
                const int pl  = (idx >> 3) & 1;
                const int c   = idx & 7;
                const __nv_bfloat16* src = pl ? pel : peh;
                cp16(&B_s[row][pl * 64 + c * 8], src + (j0 + row) * DD + c * 8);
            }
            if (jt < T) {
                const int nb = buf ^ 1;
                if (tid < 64)       cp4(&tj_s[nb][tid], etb + j0 + 64 + tid);
                else if (tid < 128) cp4(&tyj_s[nb][tid - 64], tyb + j0 + 64 + tid - 64);
            }
            cp_commit();
        }
        // scores for jt: 16 evals/thread (gate via LUT, 1 RCP each)
        {
            const float tii = ti_s[srow];
            const float* grow = &gate_s[tyi_s[srow] * NTY];
#pragma unroll 4
            for (int q = 0; q < 8; q++) {
                float sc[2];
#pragma unroll
                for (int j = 0; j < 2; j++) {
                    const int jj = sjh + 2 * q + j;
                    const float td = tii - tj_s[buf][jj];
                    const float gate = grow[tyj_s[buf][jj]];
                    const float base = __fdividef(1.0f, 1.0f + 0.5f * td * td);
                    sc[j] = (j0 + jj <= iglob) ? base * gate : 0.0f;
                }
                const __nv_bfloat162 hi2 = __floats2bfloat162_rn(sc[0], sc[1]);
                const float r0 = sc[0] - __bfloat162float(__low2bfloat16(hi2));
                const float r1 = sc[1] - __bfloat162float(__high2bfloat16(hi2));
                const __nv_bfloat162 lo2 = __floats2bfloat162_rn(r0, r1);
                *(u32*)&A_s[srow][sjh + 2 * q]      = *(const u32*)&hi2;
                *(u32*)&A_s[srow][64 + sjh + 2 * q] = *(const u32*)&lo2;
            }
        }
        cp_wait0();
        __syncthreads();

        // MMA, restructured: a_hi/a_lo loaded once per ks, both B planes once
#pragma unroll
        for (int ks = 0; ks < 4; ks++) {
            u32 ah[4], al[4];
            LDSM_X4(ah, Abase + (u32)(arow * 272 + (ks * 16 + acol) * 2));
            LDSM_X4(al, Abase + (u32)(arow * 272 + (64 + ks * 16 + acol) * 2));
#pragma unroll
            for (int i = 0; i < 2; i++) {
                const int ntg = whalf * 2 + i;
                u32 bh[4], bl[4];
                LDSM_X4T(bh, Bbase + (u32)((ks * 16 + bk) * 272 + (ntg * 16 + bn) * 2));
                LDSM_X4T(bl, Bbase + (u32)((ks * 16 + bk) * 272 + (64 + ntg * 16 + bn) * 2));
                MMA16816(acc[2 * i],     ah[0], ah[1], ah[2], ah[3], bh[0], bh[1]);
                MMA16816(acc[2 * i + 1], ah[0], ah[1], ah[2], ah[3], bh[2], bh[3]);
                MMA16816(acc[2 * i],     ah[0], ah[1], ah[2], ah[3], bl[0], bl[1]);
                MMA16816(acc[2 * i + 1], ah[0], ah[1], ah[2], ah[3], bl[2], bl[3]);
                MMA16816(acc[2 * i],     al[0], al[1], al[2], al[3], bh[0], bh[1]);
                MMA16816(acc[2 * i + 1], al[0], al[1], al[2], al[3], bh[2], bh[3]);
            }
        }
        __syncthreads();
    }

    // prefetch W_in planes into B_s for the proj MMA
    {
#pragma unroll
        for (int r = 0; r < 5; r++) {
            const int idx = tid + 256 * r;
            if (idx < 1088) cp16((char*)B_s + idx * 16, (const char*)g_winplanes + idx * 16);
        }
        cp_commit();
    }

    // LayerNorm partials (per col-half), combine via smem
#pragma unroll
    for (int h = 0; h < 2; h++) {
        const int row = 16 * wid4 + (lane >> 2) + 8 * h;
        float sum = 0.0f, sq = 0.0f;
#pragma unroll
        for (int nt = 0; nt < 4; nt++) {
#pragma unroll
            for (int j = 0; j < 2; j++) {
                const float v = acc[nt][2 * h + j];
                sum += v; sq += v * v;
            }
        }
        sum += __shfl_xor_sync(0xffffffffu, sum, 1);
        sq  += __shfl_xor_sync(0xffffffffu, sq,  1);
        sum += __shfl_xor_sync(0xffffffffu, sum, 2);
        sq  += __shfl_xor_sync(0xffffffffu, sq,  2);
        if ((lane & 3) == 0) { psum_s[whalf][row] = sum; psq_s[whalf][row] = sq; }
    }
    __syncthreads();

#pragma unroll
    for (int h = 0; h < 2; h++) {
        const int row = 16 * wid4 + (lane >> 2) + 8 * h;
        const float mu  = (psum_s[0][row] + psum_s[1][row]) * (1.0f / 64.0f);
        const float var = (psq_s[0][row] + psq_s[1][row]) * (1.0f / 64.0f) - mu * mu;
        const float inv = rsqrtf(var + 1e-6f);
        float* outp = hidden_out + ((size_t)(b * SS + T * 64 + row)) * 64;
#pragma unroll
        for (int nt = 0; nt < 4; nt++) {
            const int d0 = whalf * 32 + nt * 8 + (lane & 3) * 2;
            float2 o;
            o.x = (acc[nt][2 * h]     - mu) * inv * gm_s[d0]     + bt_s[d0];
            o.y = (acc[nt][2 * h + 1] - mu) * inv * gm_s[d0 + 1] + bt_s[d0 + 1];
            *(float2*)(outp + d0) = o;
            const __nv_bfloat162 hi2 = __floats2bfloat162_rn(o.x, o.y);
            const float r0 = o.x - __bfloat162float(__low2bfloat16(hi2));
            const float r1 = o.y - __bfloat162float(__high2bfloat16(hi2));
            const __nv_bfloat162 lo2 = __floats2bfloat162_rn(r0, r1);
            *(u32*)&A_s[row][d0]      = *(const u32*)&hi2;
            *(u32*)&A_s[row][64 + d0] = *(const u32*)&lo2;
        }
    }
    cp_wait0();
    __syncthreads();

    // proj MMA: proj = hidden @ W_in^T
#pragma unroll
    for (int n = 0; n < 4; n++)
#pragma unroll
        for (int i = 0; i < 4; i++) acc[n][i] = 0.0f;
#pragma unroll
    for (int ks = 0; ks < 4; ks++) {
        u32 ah[4], al[4];
        LDSM_X4(ah, Abase + (u32)(arow * 272 + (ks * 16 + acol) * 2));
        LDSM_X4(al, Abase + (u32)(arow * 272 + (64 + ks * 16 + acol) * 2));
#pragma unroll
        for (int i = 0; i < 2; i++) {
            const int ntg = whalf * 2 + i;
            u32 bh[4], bl[4];
            LDSM_X4T(bh, Bbase + (u32)((ks * 16 + bk) * 272 + (ntg * 16 + bn) * 2));
            LDSM_X4T(bl, Bbase + (u32)((ks * 16 + bk) * 272 + (64 + ntg * 16 + bn) * 2));
            MMA16816(acc[2 * i],     ah[0], ah[1], ah[2], ah[3], bh[0], bh[1]);
            MMA16816(acc[2 * i + 1], ah[0], ah[1], ah[2], ah[3], bh[2], bh[3]);
            MMA16816(acc[2 * i],     ah[0], ah[1], ah[2], ah[3], bl[0], bl[1]);
            MMA16816(acc[2 * i + 1], ah[0], ah[1], ah[2], ah[3], bl[2], bl[3]);
            MMA16816(acc[2 * i],     al[0], al[1], al[2], al[3], bh[0], bh[1]);
            MMA16816(acc[2 * i + 1], al[0], al[1], al[2], al[3], bh[2], bh[3]);
        }
    }
#pragma unroll
    for (int h = 0; h < 2; h++) {
        const int row = 16 * wid4 + (lane >> 2) + 8 * h;
        float* outp = g_proj + ((size_t)(b * SS + T * 64 + row)) * 64;
#pragma unroll
        for (int nt = 0; nt < 4; nt++) {
            const int d0 = whalf * 32 + nt * 8 + (lane & 3) * 2;
            float2 o;
            o.x = acc[nt][2 * h];
            o.y = acc[nt][2 * h + 1];
            *(float2*)(outp + d0) = o;
        }
    }
}

// ---------------------------------------------------------------------------
// Kernel 3: decoder on HMMA (LDSM-restructured inner loop).
// ---------------------------------------------------------------------------
__global__ __launch_bounds__(128) void decoder_hmma_kernel(
    const float* __restrict__ noise,
    const float* __restrict__ W_event,
    float* __restrict__ mean_out) {
    __shared__ __align__(16) __nv_bfloat16 A_s[64][136];
    __shared__ __align__(16) __nv_bfloat16 B_s[64][136];
    __shared__ float pj_s[8][64];
    __shared__ float wev_s[64], srow_s[64];

    const int tid  = threadIdx.x;
    const int lane = tid & 31;
    const int wid  = tid >> 5;
    const int b  = blockIdx.x >> 8;
    const int s0 = (blockIdx.x & 255) * 8;
    const int bs0 = b * SS + s0;

    {
        const char* wsrc = (const char*)g_wplanes;
#pragma unroll
        for (int r = 0; r < 9; r++) {
            const int idx = tid + 128 * r;
            if (idx < 1088) cp16((char*)B_s + idx * 16, wsrc + idx * 16);
        }
        cp16(&pj_s[0][0] + tid * 4, g_proj + (size_t)bs0 * 64 + tid * 4);
        cp_commit();
        if (tid < 64) wev_s[tid] = W_event[tid];
        for (int i = tid; i < 14 * 68; i += 128)
            ((u32*)&A_s[50][0])[i] = 0u;
    }

    float4 nreg[7];
    {
        const float4* src = (const float4*)(noise + (size_t)bs0 * NSAMP * 64);
#pragma unroll
        for (int r = 0; r < 7; r++) {
            const int idx = tid + 128 * r;
            if (idx < 800) nreg[r] = __ldg(src + idx);
        }
    }
    cp_wait0();
    __syncthreads();

    const u32 Abase = smem_u32(A_s);
    const u32 Bbase = smem_u32(B_s);
    const int arow = 16 * wid + (lane & 15);
    const int acol = (lane >> 4) * 8;
    const int bk = (lane & 7) + 8 * ((lane >> 3) & 1);
    const int bn = 8 * (lane >> 4);

    for (int c = 0; c < 8; c++) {
#pragma unroll
        for (int r = 0; r < 7; r++) {
            const int idx = tid + 128 * r;
            if (idx < 800) {
                const int row = idx >> 4, c4 = (idx & 15) * 4;
                *(uint2*)&A_s[row][c4]      = bf16x4_hi(nreg[r]);
                *(uint2*)&A_s[row][64 + c4] = bf16x4_lo(nreg[r]);
            }
        }
        __syncthreads();

        if (c < 7) {
            const float4* src =
                (const float4*)(noise + (size_t)(bs0 + c + 1) * NSAMP * 64);
#pragma unroll
            for (int r = 0; r < 7; r++) {
                const int idx = tid + 128 * r;
                if (idx < 800) nreg[r] = __ldg(src + idx);
            }
        }

        float acc[8][4];
#pragma unroll
        for (int n = 0; n < 8; n++)
#pragma unroll
            for (int i = 0; i < 4; i++) acc[n][i] = 0.0f;
#pragma unroll
        for (int ks = 0; ks < 4; ks++) {
            u32 ah[4], al[4];
            LDSM_X4(ah, Abase + (u32)(arow * 272 + (ks * 16 + acol) * 2));
            LDSM_X4(al, Abase + (u32)(arow * 272 + (64 + ks * 16 + acol) * 2));
#pragma unroll
            for (int ntp = 0; ntp < 4; ntp++) {
                u32 bh[4], bl[4];
                LDSM_X4T(bh, Bbase + (u32)((ks * 16 + bk) * 272 + (ntp * 16 + bn) * 2));
                LDSM_X4T(bl, Bbase + (u32)((ks * 16 + bk) * 272 + (64 + ntp * 16 + bn) * 2));
                MMA16816(acc[2 * ntp],     ah[0], ah[1], ah[2], ah[3], bh[0], bh[1]);
                MMA16816(acc[2 * ntp + 1], ah[0], ah[1], ah[2], ah[3], bh[2], bh[3]);
                MMA16816(acc[2 * ntp],     ah[0], ah[1], ah[2], ah[3], bl[0], bl[1]);
                MMA16816(acc[2 * ntp + 1], ah[0], ah[1], ah[2], ah[3], bl[2], bl[3]);
                MMA16816(acc[2 * ntp],     al[0], al[1], al[2], al[3], bh[0], bh[1]);
                MMA16816(acc[2 * ntp + 1], al[0], al[1], al[2], al[3], bh[2], bh[3]);
            }
        }

#pragma unroll
        for (int h = 0; h < 2; h++) {
            const int row = 16 * wid + (lane >> 2) + 8 * h;
            float g = 0.0f;
#pragma unroll
            for (int nt = 0; nt < 8; nt++) {
#pragma unroll
                for (int j = 0; j < 2; j++) {
                    const int e = nt * 8 + (lane & 3) * 2 + j;
                    const float z = acc[nt][2 * h + j] + pj_s[c][e];
                    g = fmaf(fmaxf(z, 0.0f), wev_s[e], g);
                }
            }
            g += __shfl_xor_sync(0xffffffffu, g, 1);
            g += __shfl_xor_sync(0xffffffffu, g, 2);
            if ((lane & 3) == 0 && row < NSAMP) srow_s[row] = softplusf(g);
        }
        __syncthreads();

        if (wid == 0) {
            float t = (lane < 25) ? srow_s[lane] + srow_s[lane + 25] : 0.0f;
#pragma unroll
            for (int o = 16; o > 0; o >>= 1)
                t += __shfl_xor_sync(0xffffffffu, t, o);
            if (lane == 0) mean_out[bs0 + c] = t * (1.0f / NSAMP);
        }
    }
}

// ---------------------------------------------------------------------------
extern "C" void kernel_launch(void* const* d_in, const int* in_sizes, int n_in,
                              void* d_out, int out_size) {
    const int*   event_type = (const int*)d_in[0];
    const float* event_time = (const float*)d_in[1];
    const float* noise      = (const float*)d_in[3];
    const float* Wt_pos     = (const float*)d_in[4];
    const float* type_table = (const float*)d_in[5];
    const float* gamma      = (const float*)d_in[6];
    const float* beta       = (const float*)d_in[7];
    const float* W_in       = (const float*)d_in[8];
    const float* W_noise    = (const float*)d_in[9];
    const float* W_event    = (const float*)d_in[10];

    float* out        = (float*)d_out;
    float* mean_out   = out;               // [B,S]
    float* hidden_out = out + BB * SS;     // [B,S,D]

    pe_kernel<<<(BB * SS * 32 + 255) / 256, 256>>>(event_time, Wt_pos);
    prep_w_kernel<<<32, 128>>>(W_noise, W_in, type_table);
    hidden_hmma_kernel<<<dim3(32, BB), 256>>>(event_time, event_type,
                                              gamma, beta, hidden_out);
    decoder_hmma_kernel<<<BB * SS / 8, 128>>>(noise, W_event, mean_out);
}